// round 6
// baseline (speedup 1.0000x reference)
#include <cuda_runtime.h>
#include <math.h>

// ---------------------------------------------------------------------------
// FCOS head: 5 levels x { cls tower(4x conv3x3+GN+ReLU) -> cls_pred(20)+ctr(1),
//                         box tower(4x conv3x3+GN+ReLU) -> exp(box_pred(4)*scale) }
// fp32 direct conv, GN fused: conv accumulates group stats; next conv applies
// relu(x*scale+shift) on its shared-memory load.
// ---------------------------------------------------------------------------

#define CHN 256
#define GRP 32
#define THT 8
#define TWT 16
#define COT 32
#define CICH 4
#define SPAD 19
#define CW (256*256*9)

// Scratch (no allocation allowed -> __device__ globals)
__device__ float g_bufA[2 * CHN * 100 * 100];
__device__ float g_bufB[2 * CHN * 100 * 100];
__device__ float g_stats[128];   // [b][32 groups][sum,sumsq]
__device__ float g_nsc[512];     // [b][c] norm scale
__device__ float g_nsh[512];     // [b][c] norm shift

__global__ void zero_stats_k(float* s) {
    if (threadIdx.x < 128) s[threadIdx.x] = 0.f;
}

// Tower conv: 256->256, 3x3 SAME, no bias.
// Block: 256 thr = 32 co x (8x16) px tile; thread: 4 co x 4 px.
// FIRST=true: raw input (feat). else: relu(x*nsc+nsh) applied on load.
// Accumulates (sum, sumsq) of outputs into stats (must be zero on entry).
template<bool FIRST>
__global__ __launch_bounds__(256)
void conv_tower_k(const float* __restrict__ in, float* __restrict__ out,
                  const float* __restrict__ w,
                  const float* __restrict__ nsc, const float* __restrict__ nsh,
                  float* __restrict__ stats, int H, int W, int tilesX)
{
    __shared__ __align__(16) float s_in[CICH][THT + 2][SPAD];
    __shared__ __align__(16) float s_w[CICH][9][COT];
    __shared__ float s_st[8];

    const int tid = threadIdx.x;
    const int b   = blockIdx.z;
    const int co0 = blockIdx.y * COT;
    const int ty  = blockIdx.x / tilesX;
    const int tx  = blockIdx.x - ty * tilesX;
    const int y0  = ty * THT, x0 = tx * TWT;
    const int cq  = tid >> 5;        // 0..7 channel quad
    const int pq  = tid & 31;        // pixel quad id
    const int r   = pq >> 2;         // row 0..7
    const int xq  = (pq & 3) << 2;   // col base 0,4,8,12

    float acc[4][4];
#pragma unroll
    for (int i = 0; i < 4; i++)
#pragma unroll
        for (int j = 0; j < 4; j++) acc[i][j] = 0.f;

    const float* inb  = in + (size_t)b * CHN * H * W;
    const float* nscb = FIRST ? (const float*)0 : (nsc + b * CHN);
    const float* nshb = FIRST ? (const float*)0 : (nsh + b * CHN);

    for (int ci0 = 0; ci0 < CHN; ci0 += CICH) {
        // stage input tiles (with halo, zero-padded, normalized)
#pragma unroll 1
        for (int j = tid; j < CICH * (THT + 2) * (TWT + 2); j += 256) {
            int ci  = j / ((THT + 2) * (TWT + 2));
            int rem = j - ci * ((THT + 2) * (TWT + 2));
            int iy  = rem / (TWT + 2);
            int ix  = rem - iy * (TWT + 2);
            int gy = y0 - 1 + iy, gx = x0 - 1 + ix;
            float v = 0.f;
            if ((unsigned)gy < (unsigned)H && (unsigned)gx < (unsigned)W) {
                int c = ci0 + ci;
                v = inb[((size_t)c * H + gy) * W + gx];
                if (!FIRST) v = fmaxf(fmaf(v, nscb[c], nshb[c]), 0.f);
            }
            s_in[ci][iy][ix] = v;
        }
        // stage weights: s_w[ci][k][co], co fastest (conflict-free STS)
#pragma unroll 1
        for (int j = tid; j < CICH * 9 * COT; j += 256) {
            int co = j & (COT - 1);
            int t2 = j >> 5;           // 0..CICH*9-1
            int k  = t2 % 9;
            int ci = t2 / 9;
            s_w[ci][k][co] = w[((size_t)(co0 + co) * CHN + (ci0 + ci)) * 9 + k];
        }
        __syncthreads();
#pragma unroll
        for (int ci = 0; ci < CICH; ci++) {
#pragma unroll
            for (int ky = 0; ky < 3; ky++) {
                float iv[6];
#pragma unroll
                for (int i = 0; i < 6; i++) iv[i] = s_in[ci][r + ky][xq + i];
#pragma unroll
                for (int kx = 0; kx < 3; kx++) {
                    const float4 wv = *(const float4*)&s_w[ci][ky * 3 + kx][cq << 2];
#pragma unroll
                    for (int p = 0; p < 4; p++) {
                        const float v = iv[kx + p];
                        acc[0][p] = fmaf(wv.x, v, acc[0][p]);
                        acc[1][p] = fmaf(wv.y, v, acc[1][p]);
                        acc[2][p] = fmaf(wv.z, v, acc[2][p]);
                        acc[3][p] = fmaf(wv.w, v, acc[3][p]);
                    }
                }
            }
        }
        __syncthreads();
    }

    // epilogue: store raw conv outputs + group stats
    if (tid < 8) s_st[tid] = 0.f;
    __syncthreads();

    float s = 0.f, ss = 0.f;
    float* outb = out + (size_t)b * CHN * H * W;
    const int coT = co0 + (cq << 2);
    const int gy  = y0 + r;
#pragma unroll
    for (int p = 0; p < 4; p++) {
        const int gx = x0 + xq + p;
        if (gy < H && gx < W) {
#pragma unroll
            for (int cc = 0; cc < 4; cc++) {
                float v = acc[cc][p];
                s += v;
                ss = fmaf(v, v, ss);
                outb[((size_t)(coT + cc) * H + gy) * W + gx] = v;
            }
        }
    }
    // thread's 4 consecutive channels (aligned to 4) lie in one group of 8
    const int gl = cq >> 1;  // local group 0..3
    atomicAdd(&s_st[gl * 2],     s);
    atomicAdd(&s_st[gl * 2 + 1], ss);
    __syncthreads();
    if (tid < 4) {
        const int g = (co0 >> 3) + tid;
        atomicAdd(&stats[(b * GRP + g) * 2],     s_st[tid * 2]);
        atomicAdd(&stats[(b * GRP + g) * 2 + 1], s_st[tid * 2 + 1]);
    }
}

// stats -> per-(b,c) scale/shift; then zero stats for next layer. 1 block, 512 thr.
__global__ void finalize_gn_k(const float* __restrict__ gamma,
                              const float* __restrict__ beta,
                              float invcnt, float* __restrict__ stats,
                              float* __restrict__ nsc, float* __restrict__ nsh)
{
    const int tid = threadIdx.x;
    const int b = tid >> 8, c = tid & 255, g = c >> 3;
    const float sum = stats[(b * GRP + g) * 2];
    const float sq  = stats[(b * GRP + g) * 2 + 1];
    const float mean = sum * invcnt;
    const float var  = fmaf(-mean, mean, sq * invcnt);
    const float rstd = rsqrtf(var + 1e-5f);
    const float sc = gamma[c] * rstd;
    nsc[tid] = sc;
    nsh[tid] = fmaf(-mean, sc, beta[c]);
    __syncthreads();
    if (tid < 128) stats[tid] = 0.f;
}

// Prediction conv: 256->K, 3x3 SAME, with bias. Input read as relu(x*nsc+nsh).
// EXPOUT: out = exp(v * scales[lvl]). Block: 256 thr, 16x16 px, K acc each.
template<int K, bool EXPOUT>
__global__ __launch_bounds__(256)
void pred_conv_k(const float* __restrict__ in,
                 const float* __restrict__ nsc, const float* __restrict__ nsh,
                 const float* __restrict__ w, const float* __restrict__ bias,
                 float* __restrict__ out, const float* __restrict__ scales, int lvl,
                 int H, int W, int tilesX)
{
    __shared__ float s_in[18][SPAD];
    __shared__ float s_wk[K * 9];
    const int tid = threadIdx.x;
    const int b = blockIdx.y;
    const int ty = blockIdx.x / tilesX;
    const int tx = blockIdx.x - ty * tilesX;
    const int y0 = ty * 16, x0 = tx * 16;
    const int ly = tid >> 4, lx = tid & 15;

    float acc[K];
#pragma unroll
    for (int k = 0; k < K; k++) acc[k] = bias[k];

    const float* inb  = in + (size_t)b * CHN * H * W;
    const float* nscb = nsc + b * CHN;
    const float* nshb = nsh + b * CHN;

    for (int ci = 0; ci < CHN; ci++) {
        const float sc = nscb[ci], sh = nshb[ci];
#pragma unroll 1
        for (int j = tid; j < 18 * 18; j += 256) {
            int iy = j / 18, ix = j - iy * 18;
            int gy = y0 - 1 + iy, gx = x0 - 1 + ix;
            float v = 0.f;
            if ((unsigned)gy < (unsigned)H && (unsigned)gx < (unsigned)W)
                v = fmaxf(fmaf(inb[((size_t)ci * H + gy) * W + gx], sc, sh), 0.f);
            s_in[iy][ix] = v;
        }
        if (tid < K * 9) {
            int k = tid / 9, kk = tid - k * 9;
            s_wk[tid] = w[((size_t)k * CHN + ci) * 9 + kk];
        }
        __syncthreads();
#pragma unroll
        for (int ky = 0; ky < 3; ky++)
#pragma unroll
            for (int kx = 0; kx < 3; kx++) {
                const float v = s_in[ly + ky][lx + kx];
#pragma unroll
                for (int k = 0; k < K; k++)
                    acc[k] = fmaf(v, s_wk[k * 9 + ky * 3 + kx], acc[k]);
            }
        __syncthreads();
    }

    const int gy = y0 + ly, gx = x0 + lx;
    if (gy < H && gx < W) {
        const float scl = EXPOUT ? scales[lvl] : 1.f;
#pragma unroll
        for (int k = 0; k < K; k++) {
            float v = acc[k];
            if (EXPOUT) v = expf(v * scl);
            out[((size_t)(b * K + k) * H + gy) * W + gx] = v;
        }
    }
}

extern "C" void kernel_launch(void* const* d_in, const int* in_sizes, int n_in,
                              void* d_out, int out_size)
{
    (void)in_sizes; (void)n_in; (void)out_size;

    const float* feats[5];
    for (int i = 0; i < 5; i++) feats[i] = (const float*)d_in[i];
    const float* cls_w  = (const float*)d_in[5];
    const float* cls_g  = (const float*)d_in[6];
    const float* cls_b  = (const float*)d_in[7];
    const float* box_w  = (const float*)d_in[8];
    const float* box_g  = (const float*)d_in[9];
    const float* box_b  = (const float*)d_in[10];
    const float* clsp_w = (const float*)d_in[11];
    const float* clsp_b = (const float*)d_in[12];
    const float* boxp_w = (const float*)d_in[13];
    const float* boxp_b = (const float*)d_in[14];
    const float* ctrp_w = (const float*)d_in[15];
    const float* ctrp_b = (const float*)d_in[16];
    const float* scales = (const float*)d_in[17];
    float* out = (float*)d_out;

    float *bufA, *bufB, *stats, *nsc, *nsh;
    cudaGetSymbolAddress((void**)&bufA,  g_bufA);
    cudaGetSymbolAddress((void**)&bufB,  g_bufB);
    cudaGetSymbolAddress((void**)&stats, g_stats);
    cudaGetSymbolAddress((void**)&nsc,   g_nsc);
    cudaGetSymbolAddress((void**)&nsh,   g_nsh);

    static const int HS[5] = {100, 50, 25, 13, 7};
    size_t P[6]; P[0] = 0;
    for (int i = 0; i < 5; i++) P[i + 1] = P[i] + (size_t)HS[i] * HS[i];
    const size_t S = P[5];
    const size_t box_base = 40 * S;
    const size_t ctr_base = box_base + 8 * S;

    zero_stats_k<<<1, 128>>>(stats);

    for (int lvl = 0; lvl < 5; lvl++) {
        const int H = HS[lvl], W = HS[lvl];
        const int tX = (W + TWT - 1) / TWT, tY = (H + THT - 1) / THT;
        dim3 gconv(tX * tY, CHN / COT, 2);
        const float inv = 1.f / (8.f * H * W);
        const int ptX = (W + 15) / 16, ptY = (H + 15) / 16;
        dim3 gpred(ptX * ptY, 2);

        // ---- cls tower ----
        conv_tower_k<true ><<<gconv, 256>>>(feats[lvl], bufA, cls_w,          0, 0,    stats, H, W, tX);
        finalize_gn_k<<<1, 512>>>(cls_g,       cls_b,       inv, stats, nsc, nsh);
        conv_tower_k<false><<<gconv, 256>>>(bufA, bufB, cls_w + CW,     nsc, nsh, stats, H, W, tX);
        finalize_gn_k<<<1, 512>>>(cls_g + 256, cls_b + 256, inv, stats, nsc, nsh);
        conv_tower_k<false><<<gconv, 256>>>(bufB, bufA, cls_w + 2 * CW, nsc, nsh, stats, H, W, tX);
        finalize_gn_k<<<1, 512>>>(cls_g + 512, cls_b + 512, inv, stats, nsc, nsh);
        conv_tower_k<false><<<gconv, 256>>>(bufA, bufB, cls_w + 3 * CW, nsc, nsh, stats, H, W, tX);
        finalize_gn_k<<<1, 512>>>(cls_g + 768, cls_b + 768, inv, stats, nsc, nsh);

        pred_conv_k<20, false><<<gpred, 256>>>(bufB, nsc, nsh, clsp_w, clsp_b,
                                               out + 40 * P[lvl], scales, lvl, H, W, ptX);
        pred_conv_k<1,  false><<<gpred, 256>>>(bufB, nsc, nsh, ctrp_w, ctrp_b,
                                               out + ctr_base + 2 * P[lvl], scales, lvl, H, W, ptX);

        // ---- box tower ----
        conv_tower_k<true ><<<gconv, 256>>>(feats[lvl], bufA, box_w,          0, 0,    stats, H, W, tX);
        finalize_gn_k<<<1, 512>>>(box_g,       box_b,       inv, stats, nsc, nsh);
        conv_tower_k<false><<<gconv, 256>>>(bufA, bufB, box_w + CW,     nsc, nsh, stats, H, W, tX);
        finalize_gn_k<<<1, 512>>>(box_g + 256, box_b + 256, inv, stats, nsc, nsh);
        conv_tower_k<false><<<gconv, 256>>>(bufB, bufA, box_w + 2 * CW, nsc, nsh, stats, H, W, tX);
        finalize_gn_k<<<1, 512>>>(box_g + 512, box_b + 512, inv, stats, nsc, nsh);
        conv_tower_k<false><<<gconv, 256>>>(bufA, bufB, box_w + 3 * CW, nsc, nsh, stats, H, W, tX);
        finalize_gn_k<<<1, 512>>>(box_g + 768, box_b + 768, inv, stats, nsc, nsh);

        pred_conv_k<4, true><<<gpred, 256>>>(bufB, nsc, nsh, boxp_w, boxp_b,
                                             out + box_base + 8 * P[lvl], scales, lvl, H, W, ptX);
    }
}

// round 9
// speedup vs baseline: 1.7531x; 1.7531x over previous
#include <cuda_runtime.h>
#include <math.h>

// ---------------------------------------------------------------------------
// FCOS head, fused fp32 direct conv v2.
//  - One launch per tower-layer covering ALL levels x towers x batch.
//  - Warp tile 8y x 20x (x=20 divides 100/50), thread 4co x 5px.
//  - GN fused: conv accumulates group stats; next conv applies relu(x*s+t) on
//    its smem staging load. finalize converts stats -> per-(slot,c) scale/shift.
// ---------------------------------------------------------------------------

#define CHN   256
#define CW    (256*256*9)
#define CICH  8
#define SIH   10
#define SIW   22
#define SPAD  25
#define STOT  13343            // sum of H*W over levels

// scratch: [level][tower][b][C][H*W]  => 4*256*STOT floats per buffer
__device__ float g_bufA[4 * CHN * STOT];
__device__ float g_bufB[4 * CHN * STOT];
__device__ float g_stats[1280];   // [slot(20)][group(32)][2]
__device__ float g_nsc[5120];     // [slot(20)][c(256)]
__device__ float g_nsh[5120];

struct Feat5 { const float* p[5]; };

__global__ void zero_k(float* s) {
    for (int i = threadIdx.x; i < 1280; i += 256) s[i] = 0.f;
}

// ---------------------------------------------------------------------------
// Tower conv layer: 256->256 3x3 SAME, no bias, all levels/towers/batches.
// grid = (97 tiles, 8 co-blocks, 4 = tower*2+b), block = 256.
// ---------------------------------------------------------------------------
template<bool FIRST>
__global__ __launch_bounds__(256, 3)
void conv_k(Feat5 fp, const float* __restrict__ bin, float* __restrict__ bout,
            const float* __restrict__ wcls, const float* __restrict__ wbox,
            const float* __restrict__ nsc, const float* __restrict__ nsh,
            float* __restrict__ stats)
{
    __shared__ __align__(16) float s_in[CICH][SIH][SPAD];
    __shared__ __align__(16) float s_w[CICH][9][32];
    __shared__ float s_st[8];

    const int tid = threadIdx.x;
    // ---- level lookup ----
    const int bx = blockIdx.x;
    int l = 0;
    if (bx >= 65) l = 1;
    if (bx >= 86) l = 2;
    if (bx >= 94) l = 3;
    if (bx >= 96) l = 4;
    const int HSs[5]   = {100, 50, 25, 13, 7};
    const int TBASE[5] = {0, 65, 86, 94, 96};
    const int TXN[5]   = {5, 3, 2, 1, 1};
    const int PB[5]    = {0, 10000, 12500, 13125, 13294};
    const int H = HSs[l], W = H, HW = H * W;
    const int tX = TXN[l];
    const int t  = bx - TBASE[l];
    const int ty = t / tX, tx = t - ty * tX;
    const int y0 = ty * 8, x0 = tx * 20;

    const int b   = blockIdx.z & 1;
    const int tw  = blockIdx.z >> 1;
    const int co0 = blockIdx.y << 5;
    const int slot = (l * 2 + tw) * 2 + b;          // 0..19

    const float* w = (tw ? wbox : wcls);
    const size_t lvlbase = (size_t)1024 * PB[l];    // 4*256*PB
    const float* inb;
    if (FIRST) inb = fp.p[l] + (size_t)b * CHN * HW;
    else       inb = bin + lvlbase + (size_t)((tw * 2 + b) * CHN) * HW;
    float* outb = bout + lvlbase + (size_t)((tw * 2 + b) * CHN) * HW;

    const float* nscb = nsc + slot * CHN;
    const float* nshb = nsh + slot * CHN;

    // ---- thread mapping ----
    const int wi  = tid >> 5;           // warp = co quad
    const int lane = tid & 31;
    const int r   = lane >> 2;          // row 0..7
    const int xq5 = (lane & 3) * 5;     // col base 0,5,10,15

    float acc[4][5];
#pragma unroll
    for (int i = 0; i < 4; i++)
#pragma unroll
        for (int j = 0; j < 5; j++) acc[i][j] = 0.f;

    for (int ci0 = 0; ci0 < CHN; ci0 += CICH) {
        // stage inputs (halo, zero pad, fused GN+ReLU of previous layer)
#pragma unroll 1
        for (int j = tid; j < CICH * SIH * SIW; j += 256) {
            int ci  = j / (SIH * SIW);
            int r2  = j - ci * (SIH * SIW);
            int iy  = r2 / SIW;
            int ix  = r2 - iy * SIW;
            int gy = y0 - 1 + iy, gx = x0 - 1 + ix;
            float v = 0.f;
            if ((unsigned)gy < (unsigned)H && (unsigned)gx < (unsigned)W) {
                int c = ci0 + ci;
                v = inb[(size_t)c * HW + gy * W + gx];
                if (!FIRST) v = fmaxf(fmaf(v, nscb[c], nshb[c]), 0.f);
            }
            s_in[ci][iy][ix] = v;
        }
        // stage weights: s_w[ci][k][co], co fastest (conflict-free STS)
#pragma unroll 1
        for (int j = tid; j < CICH * 288; j += 256) {
            int co = j & 31;
            int t2 = j >> 5;
            int k  = t2 % 9;
            int ci = t2 / 9;
            s_w[ci][k][co] = w[((size_t)(co0 + co) * CHN + (ci0 + ci)) * 9 + k];
        }
        __syncthreads();

#pragma unroll 2
        for (int ci = 0; ci < CICH; ci++) {
#pragma unroll
            for (int ky = 0; ky < 3; ky++) {
                float iv[7];
#pragma unroll
                for (int i2 = 0; i2 < 7; i2++) iv[i2] = s_in[ci][r + ky][xq5 + i2];
#pragma unroll
                for (int kx = 0; kx < 3; kx++) {
                    const float4 wv = *(const float4*)&s_w[ci][ky * 3 + kx][wi << 2];
#pragma unroll
                    for (int p = 0; p < 5; p++) {
                        const float v = iv[kx + p];
                        acc[0][p] = fmaf(wv.x, v, acc[0][p]);
                        acc[1][p] = fmaf(wv.y, v, acc[1][p]);
                        acc[2][p] = fmaf(wv.z, v, acc[2][p]);
                        acc[3][p] = fmaf(wv.w, v, acc[3][p]);
                    }
                }
            }
        }
        __syncthreads();
    }

    // ---- epilogue: store raw outputs + group stats ----
    if (tid < 8) s_st[tid] = 0.f;
    __syncthreads();

    float s = 0.f, ss = 0.f;
    const int coT = co0 + (wi << 2);
    const int gy  = y0 + r;
    const bool okrow = (gy < H);
#pragma unroll
    for (int p = 0; p < 5; p++) {
        const int gx = x0 + xq5 + p;
        if (okrow && gx < W) {
#pragma unroll
            for (int cc = 0; cc < 4; cc++) {
                float v = acc[cc][p];
                s += v;
                ss = fmaf(v, v, ss);
                outb[(size_t)(coT + cc) * HW + gy * W + gx] = v;
            }
        }
    }
    const int gl = wi >> 1;     // 4-co quads -> group-of-8 local index
    atomicAdd(&s_st[gl * 2],     s);
    atomicAdd(&s_st[gl * 2 + 1], ss);
    __syncthreads();
    if (tid < 4) {
        const int g = (co0 >> 3) + tid;
        atomicAdd(&stats[slot * 64 + g * 2],     s_st[tid * 2]);
        atomicAdd(&stats[slot * 64 + g * 2 + 1], s_st[tid * 2 + 1]);
    }
}

// ---------------------------------------------------------------------------
// finalize GN: stats -> per-(slot,c) scale/shift; zero stats for next layer.
// grid = 20 blocks (slot), block = 256.
// ---------------------------------------------------------------------------
__global__ void fin_k(const float* __restrict__ cg, const float* __restrict__ cb,
                      const float* __restrict__ bg, const float* __restrict__ bb,
                      float* __restrict__ stats,
                      float* __restrict__ nsc, float* __restrict__ nsh)
{
    const int slot = blockIdx.x;
    const int l  = slot >> 2;
    const int tw = (slot >> 1) & 1;
    const int c  = threadIdx.x;
    const int g  = c >> 3;
    const int HSs[5] = {100, 50, 25, 13, 7};
    const float invcnt = 1.f / (8.f * HSs[l] * HSs[l]);

    const float sum = stats[slot * 64 + g * 2];
    const float sq  = stats[slot * 64 + g * 2 + 1];
    const float mean = sum * invcnt;
    const float var  = fmaf(-mean, mean, sq * invcnt);
    const float rstd = rsqrtf(var + 1e-5f);
    const float* gam = tw ? bg : cg;
    const float* bet = tw ? bb : cb;
    const float sc = gam[c] * rstd;
    nsc[slot * 256 + c] = sc;
    nsh[slot * 256 + c] = fmaf(-mean, sc, bet[c]);
    __syncthreads();
    if (c < 64) stats[slot * 64 + c] = 0.f;
}

// ---------------------------------------------------------------------------
// cls_pred(20) + ctr_pred(1) fused as K=24 (padded), all levels. grid=(71,1,2).
// ---------------------------------------------------------------------------
__global__ __launch_bounds__(256)
void pred_cls_k(const float* __restrict__ bin,
                const float* __restrict__ nsc, const float* __restrict__ nsh,
                const float* __restrict__ clsw, const float* __restrict__ clsb,
                const float* __restrict__ ctrw, const float* __restrict__ ctrb,
                float* __restrict__ out)
{
    __shared__ __align__(16) float s_in[CICH][18][19];
    __shared__ __align__(16) float s_wk[CICH][9][24];

    const int tid = threadIdx.x;
    const int bx = blockIdx.x;
    int l = 0;
    if (bx >= 49) l = 1;
    if (bx >= 65) l = 2;
    if (bx >= 69) l = 3;
    if (bx >= 70) l = 4;
    const int HSs[5]   = {100, 50, 25, 13, 7};
    const int TBASE[5] = {0, 49, 65, 69, 70};
    const int TXN[5]   = {7, 4, 2, 1, 1};
    const int PB[5]    = {0, 10000, 12500, 13125, 13294};
    const int H = HSs[l], W = H, HW = H * W;
    const int t = bx - TBASE[l];
    const int tX = TXN[l];
    const int ty = t / tX, tx = t - ty * tX;
    const int y0 = ty * 16, x0 = tx * 16;
    const int b = blockIdx.z;
    const int slot = (l * 2 + 0) * 2 + b;   // cls tower
    const int ly = tid >> 4, lx = tid & 15;

    const float* inb  = bin + (size_t)1024 * PB[l] + (size_t)((0 * 2 + b) * CHN) * HW;
    const float* nscb = nsc + slot * CHN;
    const float* nshb = nsh + slot * CHN;

    float acc[24];
#pragma unroll
    for (int k = 0; k < 24; k++) acc[k] = 0.f;
#pragma unroll
    for (int k = 0; k < 20; k++) acc[k] = clsb[k];
    acc[20] = ctrb[0];

    for (int ci0 = 0; ci0 < CHN; ci0 += CICH) {
#pragma unroll 1
        for (int j = tid; j < CICH * 18 * 18; j += 256) {
            int ci = j / 324;
            int r2 = j - ci * 324;
            int iy = r2 / 18, ix = r2 - iy * 18;
            int gy = y0 - 1 + iy, gx = x0 - 1 + ix;
            float v = 0.f;
            if ((unsigned)gy < (unsigned)H && (unsigned)gx < (unsigned)W) {
                int c = ci0 + ci;
                v = fmaxf(fmaf(inb[(size_t)c * HW + gy * W + gx], nscb[c], nshb[c]), 0.f);
            }
            s_in[ci][iy][ix] = v;
        }
#pragma unroll 1
        for (int j = tid; j < CICH * 216; j += 256) {
            int ci = j / 216;
            int r2 = j - ci * 216;
            int kk = r2 / 24;
            int k  = r2 - kk * 24;
            int c  = ci0 + ci;
            float v = 0.f;
            if (k < 20)       v = clsw[((size_t)k * CHN + c) * 9 + kk];
            else if (k == 20) v = ctrw[(size_t)c * 9 + kk];
            s_wk[ci][kk][k] = v;
        }
        __syncthreads();
#pragma unroll 2
        for (int ci = 0; ci < CICH; ci++) {
#pragma unroll
            for (int ky = 0; ky < 3; ky++)
#pragma unroll
                for (int kx = 0; kx < 3; kx++) {
                    const float v = s_in[ci][ly + ky][lx + kx];
#pragma unroll
                    for (int kq = 0; kq < 6; kq++) {
                        const float4 wv = *(const float4*)&s_wk[ci][ky * 3 + kx][kq << 2];
                        acc[kq * 4 + 0] = fmaf(v, wv.x, acc[kq * 4 + 0]);
                        acc[kq * 4 + 1] = fmaf(v, wv.y, acc[kq * 4 + 1]);
                        acc[kq * 4 + 2] = fmaf(v, wv.z, acc[kq * 4 + 2]);
                        acc[kq * 4 + 3] = fmaf(v, wv.w, acc[kq * 4 + 3]);
                    }
                }
        }
        __syncthreads();
    }

    const int gy = y0 + ly, gx = x0 + lx;
    if (gy < H && gx < W) {
        float* lg = out + (size_t)40 * PB[l];
#pragma unroll
        for (int k = 0; k < 20; k++)
            lg[((size_t)(b * 20 + k)) * HW + gy * W + gx] = acc[k];
        out[(size_t)48 * STOT + 2 * PB[l] + (size_t)b * HW + gy * W + gx] = acc[20];
    }
}

// ---------------------------------------------------------------------------
// box_pred(4) with exp(v*scale), all levels. grid=(71,1,2).
// ---------------------------------------------------------------------------
__global__ __launch_bounds__(256)
void pred_box_k(const float* __restrict__ bin,
                const float* __restrict__ nsc, const float* __restrict__ nsh,
                const float* __restrict__ boxw, const float* __restrict__ boxb,
                const float* __restrict__ scales, float* __restrict__ out)
{
    __shared__ __align__(16) float s_in[CICH][18][19];
    __shared__ __align__(16) float s_wk[CICH][9][4];

    const int tid = threadIdx.x;
    const int bx = blockIdx.x;
    int l = 0;
    if (bx >= 49) l = 1;
    if (bx >= 65) l = 2;
    if (bx >= 69) l = 3;
    if (bx >= 70) l = 4;
    const int HSs[5]   = {100, 50, 25, 13, 7};
    const int TBASE[5] = {0, 49, 65, 69, 70};
    const int TXN[5]   = {7, 4, 2, 1, 1};
    const int PB[5]    = {0, 10000, 12500, 13125, 13294};
    const int H = HSs[l], W = H, HW = H * W;
    const int t = bx - TBASE[l];
    const int tX = TXN[l];
    const int ty = t / tX, tx = t - ty * tX;
    const int y0 = ty * 16, x0 = tx * 16;
    const int b = blockIdx.z;
    const int slot = (l * 2 + 1) * 2 + b;   // box tower
    const int ly = tid >> 4, lx = tid & 15;

    const float* inb  = bin + (size_t)1024 * PB[l] + (size_t)((1 * 2 + b) * CHN) * HW;
    const float* nscb = nsc + slot * CHN;
    const float* nshb = nsh + slot * CHN;

    float acc[4];
#pragma unroll
    for (int k = 0; k < 4; k++) acc[k] = boxb[k];

    for (int ci0 = 0; ci0 < CHN; ci0 += CICH) {
#pragma unroll 1
        for (int j = tid; j < CICH * 18 * 18; j += 256) {
            int ci = j / 324;
            int r2 = j - ci * 324;
            int iy = r2 / 18, ix = r2 - iy * 18;
            int gy = y0 - 1 + iy, gx = x0 - 1 + ix;
            float v = 0.f;
            if ((unsigned)gy < (unsigned)H && (unsigned)gx < (unsigned)W) {
                int c = ci0 + ci;
                v = fmaxf(fmaf(inb[(size_t)c * HW + gy * W + gx], nscb[c], nshb[c]), 0.f);
            }
            s_in[ci][iy][ix] = v;
        }
        // FIX(R8): was `if (tid < CICH*36)` with CICH*36 = 288 > 256 threads,
        // leaving ci=7, kk>=1 weights unstaged (garbage). Strided loop now.
#pragma unroll 1
        for (int j = tid; j < CICH * 36; j += 256) {
            int ci = j / 36;
            int r2 = j - ci * 36;
            int kk = r2 >> 2;
            int k  = r2 & 3;
            s_wk[ci][kk][k] = boxw[((size_t)k * CHN + ci0 + ci) * 9 + kk];
        }
        __syncthreads();
#pragma unroll 2
        for (int ci = 0; ci < CICH; ci++) {
#pragma unroll
            for (int ky = 0; ky < 3; ky++)
#pragma unroll
                for (int kx = 0; kx < 3; kx++) {
                    const float v = s_in[ci][ly + ky][lx + kx];
                    const float4 wv = *(const float4*)&s_wk[ci][ky * 3 + kx][0];
                    acc[0] = fmaf(v, wv.x, acc[0]);
                    acc[1] = fmaf(v, wv.y, acc[1]);
                    acc[2] = fmaf(v, wv.z, acc[2]);
                    acc[3] = fmaf(v, wv.w, acc[3]);
                }
        }
        __syncthreads();
    }

    const int gy = y0 + ly, gx = x0 + lx;
    if (gy < H && gx < W) {
        const float scl = scales[l];
        float* bo = out + (size_t)40 * STOT + 8 * PB[l];
#pragma unroll
        for (int k = 0; k < 4; k++)
            bo[((size_t)(b * 4 + k)) * HW + gy * W + gx] = expf(acc[k] * scl);
    }
}

// ---------------------------------------------------------------------------
extern "C" void kernel_launch(void* const* d_in, const int* in_sizes, int n_in,
                              void* d_out, int out_size)
{
    (void)in_sizes; (void)n_in; (void)out_size;

    Feat5 fp;
    for (int i = 0; i < 5; i++) fp.p[i] = (const float*)d_in[i];
    const float* cls_w  = (const float*)d_in[5];
    const float* cls_g  = (const float*)d_in[6];
    const float* cls_b  = (const float*)d_in[7];
    const float* box_w  = (const float*)d_in[8];
    const float* box_g  = (const float*)d_in[9];
    const float* box_b  = (const float*)d_in[10];
    const float* clsp_w = (const float*)d_in[11];
    const float* clsp_b = (const float*)d_in[12];
    const float* boxp_w = (const float*)d_in[13];
    const float* boxp_b = (const float*)d_in[14];
    const float* ctrp_w = (const float*)d_in[15];
    const float* ctrp_b = (const float*)d_in[16];
    const float* scales = (const float*)d_in[17];
    float* out = (float*)d_out;

    float *bufA, *bufB, *stats, *nsc, *nsh;
    cudaGetSymbolAddress((void**)&bufA,  g_bufA);
    cudaGetSymbolAddress((void**)&bufB,  g_bufB);
    cudaGetSymbolAddress((void**)&stats, g_stats);
    cudaGetSymbolAddress((void**)&nsc,   g_nsc);
    cudaGetSymbolAddress((void**)&nsh,   g_nsh);

    const dim3 gconv(97, 8, 4);
    const dim3 gpred(71, 1, 2);

    zero_k<<<1, 256>>>(stats);

    // layer 0: feats -> A
    conv_k<true ><<<gconv, 256>>>(fp, bufA, bufA, cls_w,          box_w,          nsc, nsh, stats);
    fin_k<<<20, 256>>>(cls_g,       cls_b,       box_g,       box_b,       stats, nsc, nsh);
    // layer 1: A -> B
    conv_k<false><<<gconv, 256>>>(fp, bufA, bufB, cls_w + CW,     box_w + CW,     nsc, nsh, stats);
    fin_k<<<20, 256>>>(cls_g + 256, cls_b + 256, box_g + 256, box_b + 256, stats, nsc, nsh);
    // layer 2: B -> A
    conv_k<false><<<gconv, 256>>>(fp, bufB, bufA, cls_w + 2 * CW, box_w + 2 * CW, nsc, nsh, stats);
    fin_k<<<20, 256>>>(cls_g + 512, cls_b + 512, box_g + 512, box_b + 512, stats, nsc, nsh);
    // layer 3: A -> B
    conv_k<false><<<gconv, 256>>>(fp, bufA, bufB, cls_w + 3 * CW, box_w + 3 * CW, nsc, nsh, stats);
    fin_k<<<20, 256>>>(cls_g + 768, cls_b + 768, box_g + 768, box_b + 768, stats, nsc, nsh);

    // predictions read layer-3 output (bufB) with its GN fused via nsc/nsh
    pred_cls_k<<<gpred, 256>>>(bufB, nsc, nsh, clsp_w, clsp_b, ctrp_w, ctrp_b, out);
    pred_box_k<<<gpred, 256>>>(bufB, nsc, nsh, boxp_w, boxp_b, scales, out);
}

// round 10
// speedup vs baseline: 1.9311x; 1.1015x over previous
#include <cuda_runtime.h>
#include <math.h>

// ---------------------------------------------------------------------------
// FCOS head, fused conv v3: packed f32x2 (FFMA2) direct conv.
//  - Thread tile 8co x 5px as 4 co-pair x 5px 64-bit accumulators.
//  - Weights staged as float2 co-pairs (LDS.64 broadcast).
//  - Inputs staged duplicated (v,v) -> one LDS.64 feeds both FFMA2 halves.
//  - Input smem row stride 28 float2: provably conflict-free lane pattern.
//  - GN fused as before (stats in conv epilogue, applied on next load).
// ---------------------------------------------------------------------------

#define CHN   256
#define CW    (256*256*9)
#define CICH  8
#define SIH   10
#define SIW   22
#define SPAD2 28               // float2 row stride; 28 = conflict-free mod 32
#define STOT  13343

__device__ float g_bufA[4 * CHN * STOT];
__device__ float g_bufB[4 * CHN * STOT];
__device__ float g_stats[1280];   // [slot(20)][group(32)][2]
__device__ float g_nsc[5120];
__device__ float g_nsh[5120];

struct Feat5 { const float* p[5]; };

__global__ void zero_k(float* s) {
    for (int i = threadIdx.x; i < 1280; i += 256) s[i] = 0.f;
}

// packed fp32x2 FMA: d = a*b + d (elementwise on two fp32 lanes)
__device__ __forceinline__ void fma2(unsigned long long& d,
                                     unsigned long long a,
                                     unsigned long long b) {
    asm("fma.rn.f32x2 %0, %1, %2, %0;" : "+l"(d) : "l"(a), "l"(b));
}

__device__ __forceinline__ float2 up2(unsigned long long v) {
    float2 f;
    asm("mov.b64 {%0, %1}, %2;" : "=f"(f.x), "=f"(f.y) : "l"(v));
    return f;
}

// ---------------------------------------------------------------------------
// Tower conv: 256->256 3x3 SAME, all levels/towers/batches in one launch.
// grid = (97 tiles, 4 co-blocks of 64, 4 = tower*2+b), block = 256.
// Warp w owns co [co0+8w, co0+8w+8) over the whole 8y x 20x spatial tile;
// lane = (row r 0..7, colquad q 0..3), thread = 8co x 5px.
// ---------------------------------------------------------------------------
template<bool FIRST>
__global__ __launch_bounds__(256, 2)
void conv_k(Feat5 fp, const float* __restrict__ bin, float* __restrict__ bout,
            const float* __restrict__ wcls, const float* __restrict__ wbox,
            const float* __restrict__ nsc, const float* __restrict__ nsh,
            float* __restrict__ stats)
{
    __shared__ __align__(16) float2 s_in2[CICH][SIH][SPAD2];
    __shared__ __align__(16) float2 s_w2[CICH][9][32];   // [ci][tap][co-pair]

    const int tid = threadIdx.x;
    const int bx = blockIdx.x;
    int l = 0;
    if (bx >= 65) l = 1;
    if (bx >= 86) l = 2;
    if (bx >= 94) l = 3;
    if (bx >= 96) l = 4;
    const int HSs[5]   = {100, 50, 25, 13, 7};
    const int TBASE[5] = {0, 65, 86, 94, 96};
    const int TXN[5]   = {5, 3, 2, 1, 1};
    const int PB[5]    = {0, 10000, 12500, 13125, 13294};
    const int H = HSs[l], W = H, HW = H * W;
    const int tX = TXN[l];
    const int t  = bx - TBASE[l];
    const int ty = t / tX, tx = t - ty * tX;
    const int y0 = ty * 8, x0 = tx * 20;

    const int b   = blockIdx.z & 1;
    const int tw  = blockIdx.z >> 1;
    const int co0 = blockIdx.y << 6;            // 64 co per block
    const int slot = (l * 2 + tw) * 2 + b;

    const float* w = (tw ? wbox : wcls);
    const size_t lvlbase = (size_t)1024 * PB[l];
    const float* inb;
    if (FIRST) inb = fp.p[l] + (size_t)b * CHN * HW;
    else       inb = bin + lvlbase + (size_t)((tw * 2 + b) * CHN) * HW;
    float* outb = bout + lvlbase + (size_t)((tw * 2 + b) * CHN) * HW;

    const float* nscb = nsc + slot * CHN;
    const float* nshb = nsh + slot * CHN;

    const int wid  = tid >> 5;
    const int lane = tid & 31;
    const int r    = lane >> 2;          // row 0..7
    const int xq5  = (lane & 3) * 5;     // col base 0,5,10,15

    unsigned long long acc[4][5];
#pragma unroll
    for (int i = 0; i < 4; i++)
#pragma unroll
        for (int j = 0; j < 5; j++) acc[i][j] = 0ull;

    for (int ci0 = 0; ci0 < CHN; ci0 += CICH) {
        // ---- stage inputs, duplicated (v,v), GN+ReLU fused ----
#pragma unroll 1
        for (int j = tid; j < CICH * SIH * SIW; j += 256) {
            int ci  = j / (SIH * SIW);
            int r2  = j - ci * (SIH * SIW);
            int iy  = r2 / SIW;
            int ix  = r2 - iy * SIW;
            int gy = y0 - 1 + iy, gx = x0 - 1 + ix;
            float v = 0.f;
            if ((unsigned)gy < (unsigned)H && (unsigned)gx < (unsigned)W) {
                int c = ci0 + ci;
                v = inb[(size_t)c * HW + gy * W + gx];
                if (!FIRST) v = fmaxf(fmaf(v, nscb[c], nshb[c]), 0.f);
            }
            s_in2[ci][iy][ix] = make_float2(v, v);
        }
        // ---- stage weights as co-pairs: s_w2[ci][tap][cp] = (w[2cp],w[2cp+1])
#pragma unroll 1
        for (int j = tid; j < CICH * 9 * 32; j += 256) {
            int cp = j & 31;
            int t2 = j >> 5;            // 0..71
            int k  = t2 % 9;
            int ci = t2 / 9;
            const float* wp = w + ((size_t)(co0 + 2 * cp) * CHN + (ci0 + ci)) * 9 + k;
            s_w2[ci][k][cp] = make_float2(wp[0], wp[CHN * 9]);
        }
        __syncthreads();

#pragma unroll 1
        for (int ci = 0; ci < CICH; ci++) {
#pragma unroll
            for (int ky = 0; ky < 3; ky++) {
                unsigned long long vv[7];
#pragma unroll
                for (int i2 = 0; i2 < 7; i2++)
                    vv[i2] = *(const unsigned long long*)&s_in2[ci][r + ky][xq5 + i2];
#pragma unroll
                for (int kx = 0; kx < 3; kx++) {
                    const unsigned long long* wp =
                        (const unsigned long long*)&s_w2[ci][ky * 3 + kx][wid << 2];
                    const unsigned long long w0 = wp[0];
                    const unsigned long long w1 = wp[1];
                    const unsigned long long w2 = wp[2];
                    const unsigned long long w3 = wp[3];
#pragma unroll
                    for (int p = 0; p < 5; p++) {
                        const unsigned long long v = vv[kx + p];
                        fma2(acc[0][p], w0, v);
                        fma2(acc[1][p], w1, v);
                        fma2(acc[2][p], w2, v);
                        fma2(acc[3][p], w3, v);
                    }
                }
            }
        }
        __syncthreads();
    }

    // ---- epilogue: unpack, store, per-warp group stats ----
    float s = 0.f, ss = 0.f;
    const int coT = co0 + (wid << 3);    // thread's 8 channels = 1 GN group
    const int gy  = y0 + r;
    const bool okrow = (gy < H);
#pragma unroll
    for (int p = 0; p < 5; p++) {
        const int gx = x0 + xq5 + p;
        if (okrow && gx < W) {
            const size_t off = (size_t)gy * W + gx;
#pragma unroll
            for (int cp = 0; cp < 4; cp++) {
                float2 f = up2(acc[cp][p]);
                outb[(size_t)(coT + 2 * cp)     * HW + off] = f.x;
                outb[(size_t)(coT + 2 * cp + 1) * HW + off] = f.y;
                s += f.x + f.y;
                ss = fmaf(f.x, f.x, ss);
                ss = fmaf(f.y, f.y, ss);
            }
        }
    }
#pragma unroll
    for (int o = 16; o > 0; o >>= 1) {
        s  += __shfl_xor_sync(0xffffffffu, s,  o);
        ss += __shfl_xor_sync(0xffffffffu, ss, o);
    }
    if (lane == 0) {
        const int g = (co0 >> 3) + wid;
        atomicAdd(&stats[slot * 64 + g * 2],     s);
        atomicAdd(&stats[slot * 64 + g * 2 + 1], ss);
    }
}

// ---------------------------------------------------------------------------
// finalize GN (unchanged from R9)
// ---------------------------------------------------------------------------
__global__ void fin_k(const float* __restrict__ cg, const float* __restrict__ cb,
                      const float* __restrict__ bg, const float* __restrict__ bb,
                      float* __restrict__ stats,
                      float* __restrict__ nsc, float* __restrict__ nsh)
{
    const int slot = blockIdx.x;
    const int l  = slot >> 2;
    const int tw = (slot >> 1) & 1;
    const int c  = threadIdx.x;
    const int g  = c >> 3;
    const int HSs[5] = {100, 50, 25, 13, 7};
    const float invcnt = 1.f / (8.f * HSs[l] * HSs[l]);

    const float sum = stats[slot * 64 + g * 2];
    const float sq  = stats[slot * 64 + g * 2 + 1];
    const float mean = sum * invcnt;
    const float var  = fmaf(-mean, mean, sq * invcnt);
    const float rstd = rsqrtf(var + 1e-5f);
    const float* gam = tw ? bg : cg;
    const float* bet = tw ? bb : cb;
    const float sc = gam[c] * rstd;
    nsc[slot * 256 + c] = sc;
    nsh[slot * 256 + c] = fmaf(-mean, sc, bet[c]);
    __syncthreads();
    if (c < 64) stats[slot * 64 + c] = 0.f;
}

// ---------------------------------------------------------------------------
// cls_pred(20) + ctr_pred(1) fused (unchanged from R9, passing)
// ---------------------------------------------------------------------------
__global__ __launch_bounds__(256)
void pred_cls_k(const float* __restrict__ bin,
                const float* __restrict__ nsc, const float* __restrict__ nsh,
                const float* __restrict__ clsw, const float* __restrict__ clsb,
                const float* __restrict__ ctrw, const float* __restrict__ ctrb,
                float* __restrict__ out)
{
    __shared__ __align__(16) float s_in[CICH][18][19];
    __shared__ __align__(16) float s_wk[CICH][9][24];

    const int tid = threadIdx.x;
    const int bx = blockIdx.x;
    int l = 0;
    if (bx >= 49) l = 1;
    if (bx >= 65) l = 2;
    if (bx >= 69) l = 3;
    if (bx >= 70) l = 4;
    const int HSs[5]   = {100, 50, 25, 13, 7};
    const int TBASE[5] = {0, 49, 65, 69, 70};
    const int TXN[5]   = {7, 4, 2, 1, 1};
    const int PB[5]    = {0, 10000, 12500, 13125, 13294};
    const int H = HSs[l], W = H, HW = H * W;
    const int t = bx - TBASE[l];
    const int tX = TXN[l];
    const int ty = t / tX, tx = t - ty * tX;
    const int y0 = ty * 16, x0 = tx * 16;
    const int b = blockIdx.z;
    const int slot = (l * 2 + 0) * 2 + b;
    const int ly = tid >> 4, lx = tid & 15;

    const float* inb  = bin + (size_t)1024 * PB[l] + (size_t)((0 * 2 + b) * CHN) * HW;
    const float* nscb = nsc + slot * CHN;
    const float* nshb = nsh + slot * CHN;

    float acc[24];
#pragma unroll
    for (int k = 0; k < 24; k++) acc[k] = 0.f;
#pragma unroll
    for (int k = 0; k < 20; k++) acc[k] = clsb[k];
    acc[20] = ctrb[0];

    for (int ci0 = 0; ci0 < CHN; ci0 += CICH) {
#pragma unroll 1
        for (int j = tid; j < CICH * 18 * 18; j += 256) {
            int ci = j / 324;
            int r2 = j - ci * 324;
            int iy = r2 / 18, ix = r2 - iy * 18;
            int gy = y0 - 1 + iy, gx = x0 - 1 + ix;
            float v = 0.f;
            if ((unsigned)gy < (unsigned)H && (unsigned)gx < (unsigned)W) {
                int c = ci0 + ci;
                v = fmaxf(fmaf(inb[(size_t)c * HW + gy * W + gx], nscb[c], nshb[c]), 0.f);
            }
            s_in[ci][iy][ix] = v;
        }
#pragma unroll 1
        for (int j = tid; j < CICH * 216; j += 256) {
            int ci = j / 216;
            int r2 = j - ci * 216;
            int kk = r2 / 24;
            int k  = r2 - kk * 24;
            int c  = ci0 + ci;
            float v = 0.f;
            if (k < 20)       v = clsw[((size_t)k * CHN + c) * 9 + kk];
            else if (k == 20) v = ctrw[(size_t)c * 9 + kk];
            s_wk[ci][kk][k] = v;
        }
        __syncthreads();
#pragma unroll 2
        for (int ci = 0; ci < CICH; ci++) {
#pragma unroll
            for (int ky = 0; ky < 3; ky++)
#pragma unroll
                for (int kx = 0; kx < 3; kx++) {
                    const float v = s_in[ci][ly + ky][lx + kx];
#pragma unroll
                    for (int kq = 0; kq < 6; kq++) {
                        const float4 wv = *(const float4*)&s_wk[ci][ky * 3 + kx][kq << 2];
                        acc[kq * 4 + 0] = fmaf(v, wv.x, acc[kq * 4 + 0]);
                        acc[kq * 4 + 1] = fmaf(v, wv.y, acc[kq * 4 + 1]);
                        acc[kq * 4 + 2] = fmaf(v, wv.z, acc[kq * 4 + 2]);
                        acc[kq * 4 + 3] = fmaf(v, wv.w, acc[kq * 4 + 3]);
                    }
                }
        }
        __syncthreads();
    }

    const int gy = y0 + ly, gx = x0 + lx;
    if (gy < H && gx < W) {
        float* lg = out + (size_t)40 * PB[l];
#pragma unroll
        for (int k = 0; k < 20; k++)
            lg[((size_t)(b * 20 + k)) * HW + gy * W + gx] = acc[k];
        out[(size_t)48 * STOT + 2 * PB[l] + (size_t)b * HW + gy * W + gx] = acc[20];
    }
}

// ---------------------------------------------------------------------------
// box_pred(4) with exp(v*scale) (unchanged from R9, passing)
// ---------------------------------------------------------------------------
__global__ __launch_bounds__(256)
void pred_box_k(const float* __restrict__ bin,
                const float* __restrict__ nsc, const float* __restrict__ nsh,
                const float* __restrict__ boxw, const float* __restrict__ boxb,
                const float* __restrict__ scales, float* __restrict__ out)
{
    __shared__ __align__(16) float s_in[CICH][18][19];
    __shared__ __align__(16) float s_wk[CICH][9][4];

    const int tid = threadIdx.x;
    const int bx = blockIdx.x;
    int l = 0;
    if (bx >= 49) l = 1;
    if (bx >= 65) l = 2;
    if (bx >= 69) l = 3;
    if (bx >= 70) l = 4;
    const int HSs[5]   = {100, 50, 25, 13, 7};
    const int TBASE[5] = {0, 49, 65, 69, 70};
    const int TXN[5]   = {7, 4, 2, 1, 1};
    const int PB[5]    = {0, 10000, 12500, 13125, 13294};
    const int H = HSs[l], W = H, HW = H * W;
    const int t = bx - TBASE[l];
    const int tX = TXN[l];
    const int ty = t / tX, tx = t - ty * tX;
    const int y0 = ty * 16, x0 = tx * 16;
    const int b = blockIdx.z;
    const int slot = (l * 2 + 1) * 2 + b;
    const int ly = tid >> 4, lx = tid & 15;

    const float* inb  = bin + (size_t)1024 * PB[l] + (size_t)((1 * 2 + b) * CHN) * HW;
    const float* nscb = nsc + slot * CHN;
    const float* nshb = nsh + slot * CHN;

    float acc[4];
#pragma unroll
    for (int k = 0; k < 4; k++) acc[k] = boxb[k];

    for (int ci0 = 0; ci0 < CHN; ci0 += CICH) {
#pragma unroll 1
        for (int j = tid; j < CICH * 18 * 18; j += 256) {
            int ci = j / 324;
            int r2 = j - ci * 324;
            int iy = r2 / 18, ix = r2 - iy * 18;
            int gy = y0 - 1 + iy, gx = x0 - 1 + ix;
            float v = 0.f;
            if ((unsigned)gy < (unsigned)H && (unsigned)gx < (unsigned)W) {
                int c = ci0 + ci;
                v = fmaxf(fmaf(inb[(size_t)c * HW + gy * W + gx], nscb[c], nshb[c]), 0.f);
            }
            s_in[ci][iy][ix] = v;
        }
#pragma unroll 1
        for (int j = tid; j < CICH * 36; j += 256) {
            int ci = j / 36;
            int r2 = j - ci * 36;
            int kk = r2 >> 2;
            int k  = r2 & 3;
            s_wk[ci][kk][k] = boxw[((size_t)k * CHN + ci0 + ci) * 9 + kk];
        }
        __syncthreads();
#pragma unroll 2
        for (int ci = 0; ci < CICH; ci++) {
#pragma unroll
            for (int ky = 0; ky < 3; ky++)
#pragma unroll
                for (int kx = 0; kx < 3; kx++) {
                    const float v = s_in[ci][ly + ky][lx + kx];
                    const float4 wv = *(const float4*)&s_wk[ci][ky * 3 + kx][0];
                    acc[0] = fmaf(v, wv.x, acc[0]);
                    acc[1] = fmaf(v, wv.y, acc[1]);
                    acc[2] = fmaf(v, wv.z, acc[2]);
                    acc[3] = fmaf(v, wv.w, acc[3]);
                }
        }
        __syncthreads();
    }

    const int gy = y0 + ly, gx = x0 + lx;
    if (gy < H && gx < W) {
        const float scl = scales[l];
        float* bo = out + (size_t)40 * STOT + 8 * PB[l];
#pragma unroll
        for (int k = 0; k < 4; k++)
            bo[((size_t)(b * 4 + k)) * HW + gy * W + gx] = expf(acc[k] * scl);
    }
}

// ---------------------------------------------------------------------------
extern "C" void kernel_launch(void* const* d_in, const int* in_sizes, int n_in,
                              void* d_out, int out_size)
{
    (void)in_sizes; (void)n_in; (void)out_size;

    Feat5 fp;
    for (int i = 0; i < 5; i++) fp.p[i] = (const float*)d_in[i];
    const float* cls_w  = (const float*)d_in[5];
    const float* cls_g  = (const float*)d_in[6];
    const float* cls_b  = (const float*)d_in[7];
    const float* box_w  = (const float*)d_in[8];
    const float* box_g  = (const float*)d_in[9];
    const float* box_b  = (const float*)d_in[10];
    const float* clsp_w = (const float*)d_in[11];
    const float* clsp_b = (const float*)d_in[12];
    const float* boxp_w = (const float*)d_in[13];
    const float* boxp_b = (const float*)d_in[14];
    const float* ctrp_w = (const float*)d_in[15];
    const float* ctrp_b = (const float*)d_in[16];
    const float* scales = (const float*)d_in[17];
    float* out = (float*)d_out;

    float *bufA, *bufB, *stats, *nsc, *nsh;
    cudaGetSymbolAddress((void**)&bufA,  g_bufA);
    cudaGetSymbolAddress((void**)&bufB,  g_bufB);
    cudaGetSymbolAddress((void**)&stats, g_stats);
    cudaGetSymbolAddress((void**)&nsc,   g_nsc);
    cudaGetSymbolAddress((void**)&nsh,   g_nsh);

    const dim3 gconv(97, 4, 4);     // 64 co per co-block now
    const dim3 gpred(71, 1, 2);

    zero_k<<<1, 256>>>(stats);

    conv_k<true ><<<gconv, 256>>>(fp, bufA, bufA, cls_w,          box_w,          nsc, nsh, stats);
    fin_k<<<20, 256>>>(cls_g,       cls_b,       box_g,       box_b,       stats, nsc, nsh);
    conv_k<false><<<gconv, 256>>>(fp, bufA, bufB, cls_w + CW,     box_w + CW,     nsc, nsh, stats);
    fin_k<<<20, 256>>>(cls_g + 256, cls_b + 256, box_g + 256, box_b + 256, stats, nsc, nsh);
    conv_k<false><<<gconv, 256>>>(fp, bufB, bufA, cls_w + 2 * CW, box_w + 2 * CW, nsc, nsh, stats);
    fin_k<<<20, 256>>>(cls_g + 512, cls_b + 512, box_g + 512, box_b + 512, stats, nsc, nsh);
    conv_k<false><<<gconv, 256>>>(fp, bufA, bufB, cls_w + 3 * CW, box_w + 3 * CW, nsc, nsh, stats);
    fin_k<<<20, 256>>>(cls_g + 768, cls_b + 768, box_g + 768, box_b + 768, stats, nsc, nsh);

    pred_cls_k<<<gpred, 256>>>(bufB, nsc, nsh, clsp_w, clsp_b, ctrp_w, ctrp_b, out);
    pred_box_k<<<gpred, 256>>>(bufB, nsc, nsh, boxp_w, boxp_b, scales, out);
}

// round 11
// speedup vs baseline: 2.3113x; 1.1969x over previous
#include <cuda_runtime.h>
#include <math.h>

// ---------------------------------------------------------------------------
// FCOS head, fused conv v4: FFMA2 direct conv, scalar-input smem + reg pack.
//  - Thread tile 8co x 5px as 4 co-pair x 5px 64-bit accumulators (FFMA2).
//  - Inputs staged as scalar fp32 (stride 28 -> conflict-free); packed (v,v)
//    into u64 via mov.b64 in registers (1 wavefront per LDS instead of 2).
//  - Weights staged as float2 co-pairs (broadcast LDS).
//  - Staging: each thread owns one fixed halo pixel, loops channels (no
//    div/mod in hot loop).
//  - 3 blocks/SM via launch_bounds + 27KB smem.
// ---------------------------------------------------------------------------

#define CHN   256
#define CW    (256*256*9)
#define CICH  8
#define SIH   10
#define SIW   22
#define SPADF 28               // float row stride; 28r+5q+i distinct mod 32
#define STOT  13343

__device__ float g_bufA[4 * CHN * STOT];
__device__ float g_bufB[4 * CHN * STOT];
__device__ float g_stats[1280];   // [slot(20)][group(32)][2]
__device__ float g_nsc[5120];
__device__ float g_nsh[5120];

struct Feat5 { const float* p[5]; };

__global__ void zero_k(float* s) {
    for (int i = threadIdx.x; i < 1280; i += 256) s[i] = 0.f;
}

__device__ __forceinline__ void fma2(unsigned long long& d,
                                     unsigned long long a,
                                     unsigned long long b) {
    asm("fma.rn.f32x2 %0, %1, %2, %0;" : "+l"(d) : "l"(a), "l"(b));
}

__device__ __forceinline__ unsigned long long dup2(float v) {
    unsigned long long d;
    asm("mov.b64 %0, {%1, %1};" : "=l"(d) : "f"(v));
    return d;
}

__device__ __forceinline__ float2 up2(unsigned long long v) {
    float2 f;
    asm("mov.b64 {%0, %1}, %2;" : "=f"(f.x), "=f"(f.y) : "l"(v));
    return f;
}

// ---------------------------------------------------------------------------
// Tower conv: 256->256 3x3 SAME, all levels/towers/batches in one launch.
// grid = (97 tiles, 4 co-blocks of 64, 4 = tower*2+b), block = 256.
// Warp w owns co [co0+8w, co0+8w+8); lane = (row r 0..7, colquad q 0..3).
// ---------------------------------------------------------------------------
template<bool FIRST>
__global__ __launch_bounds__(256, 3)
void conv_k(Feat5 fp, const float* __restrict__ bin, float* __restrict__ bout,
            const float* __restrict__ wcls, const float* __restrict__ wbox,
            const float* __restrict__ nsc, const float* __restrict__ nsh,
            float* __restrict__ stats)
{
    __shared__ __align__(16) float  s_in[CICH][SIH][SPADF];
    __shared__ __align__(16) float2 s_w2[CICH][9][32];   // [ci][tap][co-pair]

    const int tid = threadIdx.x;
    const int bx = blockIdx.x;
    int l = 0;
    if (bx >= 65) l = 1;
    if (bx >= 86) l = 2;
    if (bx >= 94) l = 3;
    if (bx >= 96) l = 4;
    const int HSs[5]   = {100, 50, 25, 13, 7};
    const int TBASE[5] = {0, 65, 86, 94, 96};
    const int TXN[5]   = {5, 3, 2, 1, 1};
    const int PB[5]    = {0, 10000, 12500, 13125, 13294};
    const int H = HSs[l], W = H, HW = H * W;
    const int tX = TXN[l];
    const int t  = bx - TBASE[l];
    const int ty = t / tX, tx = t - ty * tX;
    const int y0 = ty * 8, x0 = tx * 20;

    const int b   = blockIdx.z & 1;
    const int tw  = blockIdx.z >> 1;
    const int co0 = blockIdx.y << 6;            // 64 co per block
    const int slot = (l * 2 + tw) * 2 + b;

    const float* w = (tw ? wbox : wcls);
    const size_t lvlbase = (size_t)1024 * PB[l];
    const float* inb;
    if (FIRST) inb = fp.p[l] + (size_t)b * CHN * HW;
    else       inb = bin + lvlbase + (size_t)((tw * 2 + b) * CHN) * HW;
    float* outb = bout + lvlbase + (size_t)((tw * 2 + b) * CHN) * HW;

    const float* nscb = nsc + slot * CHN;
    const float* nshb = nsh + slot * CHN;

    const int wid  = tid >> 5;
    const int lane = tid & 31;
    const int r    = lane >> 2;          // row 0..7
    const int xq5  = (lane & 3) * 5;     // col base 0,5,10,15

    // ---- fixed staging assignment: thread owns one halo pixel ----
    const int  sIY = tid / SIW;                  // 0..11 (valid < SIH)
    const int  sIX = tid - sIY * SIW;
    const bool sAct = (tid < SIH * SIW);         // 220 active
    const int  sgy = y0 - 1 + sIY, sgx = x0 - 1 + sIX;
    const bool sIn = sAct && (unsigned)sgy < (unsigned)H &&
                             (unsigned)sgx < (unsigned)W;
    const float* sPtr = inb + (size_t)sgy * W + sgx;   // valid only if sIn

    unsigned long long acc[4][5];
#pragma unroll
    for (int i = 0; i < 4; i++)
#pragma unroll
        for (int j = 0; j < 5; j++) acc[i][j] = 0ull;

    for (int ci0 = 0; ci0 < CHN; ci0 += CICH) {
        // ---- stage inputs: 8 channels of this thread's halo pixel ----
        if (sAct) {
#pragma unroll
            for (int ci = 0; ci < CICH; ci++) {
                float v = 0.f;
                if (sIn) {
                    const int c = ci0 + ci;
                    v = sPtr[(size_t)c * HW];
                    if (!FIRST) v = fmaxf(fmaf(v, nscb[c], nshb[c]), 0.f);
                }
                s_in[ci][sIY][sIX] = v;
            }
        }
        // ---- stage weights as co-pairs ----
#pragma unroll 1
        for (int j = tid; j < CICH * 9 * 32; j += 256) {
            int cp = j & 31;
            int t2 = j >> 5;            // 0..71
            int k  = t2 % 9;
            int ci = t2 / 9;
            const float* wp = w + ((size_t)(co0 + 2 * cp) * CHN + (ci0 + ci)) * 9 + k;
            s_w2[ci][k][cp] = make_float2(wp[0], wp[CHN * 9]);
        }
        __syncthreads();

#pragma unroll 1
        for (int ci = 0; ci < CICH; ci++) {
#pragma unroll
            for (int ky = 0; ky < 3; ky++) {
                unsigned long long vv[7];
#pragma unroll
                for (int i2 = 0; i2 < 7; i2++)
                    vv[i2] = dup2(s_in[ci][r + ky][xq5 + i2]);
#pragma unroll
                for (int kx = 0; kx < 3; kx++) {
                    const unsigned long long* wp =
                        (const unsigned long long*)&s_w2[ci][ky * 3 + kx][wid << 2];
                    const unsigned long long w0 = wp[0];
                    const unsigned long long w1 = wp[1];
                    const unsigned long long w2 = wp[2];
                    const unsigned long long w3 = wp[3];
#pragma unroll
                    for (int p = 0; p < 5; p++) {
                        const unsigned long long v = vv[kx + p];
                        fma2(acc[0][p], w0, v);
                        fma2(acc[1][p], w1, v);
                        fma2(acc[2][p], w2, v);
                        fma2(acc[3][p], w3, v);
                    }
                }
            }
        }
        __syncthreads();
    }

    // ---- epilogue: unpack, store, per-warp group stats ----
    float s = 0.f, ss = 0.f;
    const int coT = co0 + (wid << 3);    // thread's 8 channels = 1 GN group
    const int gy  = y0 + r;
    const bool okrow = (gy < H);
#pragma unroll
    for (int p = 0; p < 5; p++) {
        const int gx = x0 + xq5 + p;
        if (okrow && gx < W) {
            const size_t off = (size_t)gy * W + gx;
#pragma unroll
            for (int cp = 0; cp < 4; cp++) {
                float2 f = up2(acc[cp][p]);
                outb[(size_t)(coT + 2 * cp)     * HW + off] = f.x;
                outb[(size_t)(coT + 2 * cp + 1) * HW + off] = f.y;
                s += f.x + f.y;
                ss = fmaf(f.x, f.x, ss);
                ss = fmaf(f.y, f.y, ss);
            }
        }
    }
#pragma unroll
    for (int o = 16; o > 0; o >>= 1) {
        s  += __shfl_xor_sync(0xffffffffu, s,  o);
        ss += __shfl_xor_sync(0xffffffffu, ss, o);
    }
    if (lane == 0) {
        const int g = (co0 >> 3) + wid;
        atomicAdd(&stats[slot * 64 + g * 2],     s);
        atomicAdd(&stats[slot * 64 + g * 2 + 1], ss);
    }
}

// ---------------------------------------------------------------------------
// finalize GN (unchanged)
// ---------------------------------------------------------------------------
__global__ void fin_k(const float* __restrict__ cg, const float* __restrict__ cb,
                      const float* __restrict__ bg, const float* __restrict__ bb,
                      float* __restrict__ stats,
                      float* __restrict__ nsc, float* __restrict__ nsh)
{
    const int slot = blockIdx.x;
    const int l  = slot >> 2;
    const int tw = (slot >> 1) & 1;
    const int c  = threadIdx.x;
    const int g  = c >> 3;
    const int HSs[5] = {100, 50, 25, 13, 7};
    const float invcnt = 1.f / (8.f * HSs[l] * HSs[l]);

    const float sum = stats[slot * 64 + g * 2];
    const float sq  = stats[slot * 64 + g * 2 + 1];
    const float mean = sum * invcnt;
    const float var  = fmaf(-mean, mean, sq * invcnt);
    const float rstd = rsqrtf(var + 1e-5f);
    const float* gam = tw ? bg : cg;
    const float* bet = tw ? bb : cb;
    const float sc = gam[c] * rstd;
    nsc[slot * 256 + c] = sc;
    nsh[slot * 256 + c] = fmaf(-mean, sc, bet[c]);
    __syncthreads();
    if (c < 64) stats[slot * 64 + c] = 0.f;
}

// ---------------------------------------------------------------------------
// cls_pred(20) + ctr_pred(1) fused (unchanged, passing)
// ---------------------------------------------------------------------------
__global__ __launch_bounds__(256)
void pred_cls_k(const float* __restrict__ bin,
                const float* __restrict__ nsc, const float* __restrict__ nsh,
                const float* __restrict__ clsw, const float* __restrict__ clsb,
                const float* __restrict__ ctrw, const float* __restrict__ ctrb,
                float* __restrict__ out)
{
    __shared__ __align__(16) float s_in[CICH][18][19];
    __shared__ __align__(16) float s_wk[CICH][9][24];

    const int tid = threadIdx.x;
    const int bx = blockIdx.x;
    int l = 0;
    if (bx >= 49) l = 1;
    if (bx >= 65) l = 2;
    if (bx >= 69) l = 3;
    if (bx >= 70) l = 4;
    const int HSs[5]   = {100, 50, 25, 13, 7};
    const int TBASE[5] = {0, 49, 65, 69, 70};
    const int TXN[5]   = {7, 4, 2, 1, 1};
    const int PB[5]    = {0, 10000, 12500, 13125, 13294};
    const int H = HSs[l], W = H, HW = H * W;
    const int t = bx - TBASE[l];
    const int tX = TXN[l];
    const int ty = t / tX, tx = t - ty * tX;
    const int y0 = ty * 16, x0 = tx * 16;
    const int b = blockIdx.z;
    const int slot = (l * 2 + 0) * 2 + b;
    const int ly = tid >> 4, lx = tid & 15;

    const float* inb  = bin + (size_t)1024 * PB[l] + (size_t)((0 * 2 + b) * CHN) * HW;
    const float* nscb = nsc + slot * CHN;
    const float* nshb = nsh + slot * CHN;

    float acc[24];
#pragma unroll
    for (int k = 0; k < 24; k++) acc[k] = 0.f;
#pragma unroll
    for (int k = 0; k < 20; k++) acc[k] = clsb[k];
    acc[20] = ctrb[0];

    for (int ci0 = 0; ci0 < CHN; ci0 += CICH) {
#pragma unroll 1
        for (int j = tid; j < CICH * 18 * 18; j += 256) {
            int ci = j / 324;
            int r2 = j - ci * 324;
            int iy = r2 / 18, ix = r2 - iy * 18;
            int gy = y0 - 1 + iy, gx = x0 - 1 + ix;
            float v = 0.f;
            if ((unsigned)gy < (unsigned)H && (unsigned)gx < (unsigned)W) {
                int c = ci0 + ci;
                v = fmaxf(fmaf(inb[(size_t)c * HW + gy * W + gx], nscb[c], nshb[c]), 0.f);
            }
            s_in[ci][iy][ix] = v;
        }
#pragma unroll 1
        for (int j = tid; j < CICH * 216; j += 256) {
            int ci = j / 216;
            int r2 = j - ci * 216;
            int kk = r2 / 24;
            int k  = r2 - kk * 24;
            int c  = ci0 + ci;
            float v = 0.f;
            if (k < 20)       v = clsw[((size_t)k * CHN + c) * 9 + kk];
            else if (k == 20) v = ctrw[(size_t)c * 9 + kk];
            s_wk[ci][kk][k] = v;
        }
        __syncthreads();
#pragma unroll 2
        for (int ci = 0; ci < CICH; ci++) {
#pragma unroll
            for (int ky = 0; ky < 3; ky++)
#pragma unroll
                for (int kx = 0; kx < 3; kx++) {
                    const float v = s_in[ci][ly + ky][lx + kx];
#pragma unroll
                    for (int kq = 0; kq < 6; kq++) {
                        const float4 wv = *(const float4*)&s_wk[ci][ky * 3 + kx][kq << 2];
                        acc[kq * 4 + 0] = fmaf(v, wv.x, acc[kq * 4 + 0]);
                        acc[kq * 4 + 1] = fmaf(v, wv.y, acc[kq * 4 + 1]);
                        acc[kq * 4 + 2] = fmaf(v, wv.z, acc[kq * 4 + 2]);
                        acc[kq * 4 + 3] = fmaf(v, wv.w, acc[kq * 4 + 3]);
                    }
                }
        }
        __syncthreads();
    }

    const int gy = y0 + ly, gx = x0 + lx;
    if (gy < H && gx < W) {
        float* lg = out + (size_t)40 * PB[l];
#pragma unroll
        for (int k = 0; k < 20; k++)
            lg[((size_t)(b * 20 + k)) * HW + gy * W + gx] = acc[k];
        out[(size_t)48 * STOT + 2 * PB[l] + (size_t)b * HW + gy * W + gx] = acc[20];
    }
}

// ---------------------------------------------------------------------------
// box_pred(4) with exp(v*scale) (unchanged, passing)
// ---------------------------------------------------------------------------
__global__ __launch_bounds__(256)
void pred_box_k(const float* __restrict__ bin,
                const float* __restrict__ nsc, const float* __restrict__ nsh,
                const float* __restrict__ boxw, const float* __restrict__ boxb,
                const float* __restrict__ scales, float* __restrict__ out)
{
    __shared__ __align__(16) float s_in[CICH][18][19];
    __shared__ __align__(16) float s_wk[CICH][9][4];

    const int tid = threadIdx.x;
    const int bx = blockIdx.x;
    int l = 0;
    if (bx >= 49) l = 1;
    if (bx >= 65) l = 2;
    if (bx >= 69) l = 3;
    if (bx >= 70) l = 4;
    const int HSs[5]   = {100, 50, 25, 13, 7};
    const int TBASE[5] = {0, 49, 65, 69, 70};
    const int TXN[5]   = {7, 4, 2, 1, 1};
    const int PB[5]    = {0, 10000, 12500, 13125, 13294};
    const int H = HSs[l], W = H, HW = H * W;
    const int t = bx - TBASE[l];
    const int tX = TXN[l];
    const int ty = t / tX, tx = t - ty * tX;
    const int y0 = ty * 16, x0 = tx * 16;
    const int b = blockIdx.z;
    const int slot = (l * 2 + 1) * 2 + b;
    const int ly = tid >> 4, lx = tid & 15;

    const float* inb  = bin + (size_t)1024 * PB[l] + (size_t)((1 * 2 + b) * CHN) * HW;
    const float* nscb = nsc + slot * CHN;
    const float* nshb = nsh + slot * CHN;

    float acc[4];
#pragma unroll
    for (int k = 0; k < 4; k++) acc[k] = boxb[k];

    for (int ci0 = 0; ci0 < CHN; ci0 += CICH) {
#pragma unroll 1
        for (int j = tid; j < CICH * 18 * 18; j += 256) {
            int ci = j / 324;
            int r2 = j - ci * 324;
            int iy = r2 / 18, ix = r2 - iy * 18;
            int gy = y0 - 1 + iy, gx = x0 - 1 + ix;
            float v = 0.f;
            if ((unsigned)gy < (unsigned)H && (unsigned)gx < (unsigned)W) {
                int c = ci0 + ci;
                v = fmaxf(fmaf(inb[(size_t)c * HW + gy * W + gx], nscb[c], nshb[c]), 0.f);
            }
            s_in[ci][iy][ix] = v;
        }
#pragma unroll 1
        for (int j = tid; j < CICH * 36; j += 256) {
            int ci = j / 36;
            int r2 = j - ci * 36;
            int kk = r2 >> 2;
            int k  = r2 & 3;
            s_wk[ci][kk][k] = boxw[((size_t)k * CHN + ci0 + ci) * 9 + kk];
        }
        __syncthreads();
#pragma unroll 2
        for (int ci = 0; ci < CICH; ci++) {
#pragma unroll
            for (int ky = 0; ky < 3; ky++)
#pragma unroll
                for (int kx = 0; kx < 3; kx++) {
                    const float v = s_in[ci][ly + ky][lx + kx];
                    const float4 wv = *(const float4*)&s_wk[ci][ky * 3 + kx][0];
                    acc[0] = fmaf(v, wv.x, acc[0]);
                    acc[1] = fmaf(v, wv.y, acc[1]);
                    acc[2] = fmaf(v, wv.z, acc[2]);
                    acc[3] = fmaf(v, wv.w, acc[3]);
                }
        }
        __syncthreads();
    }

    const int gy = y0 + ly, gx = x0 + lx;
    if (gy < H && gx < W) {
        const float scl = scales[l];
        float* bo = out + (size_t)40 * STOT + 8 * PB[l];
#pragma unroll
        for (int k = 0; k < 4; k++)
            bo[((size_t)(b * 4 + k)) * HW + gy * W + gx] = expf(acc[k] * scl);
    }
}

// ---------------------------------------------------------------------------
extern "C" void kernel_launch(void* const* d_in, const int* in_sizes, int n_in,
                              void* d_out, int out_size)
{
    (void)in_sizes; (void)n_in; (void)out_size;

    Feat5 fp;
    for (int i = 0; i < 5; i++) fp.p[i] = (const float*)d_in[i];
    const float* cls_w  = (const float*)d_in[5];
    const float* cls_g  = (const float*)d_in[6];
    const float* cls_b  = (const float*)d_in[7];
    const float* box_w  = (const float*)d_in[8];
    const float* box_g  = (const float*)d_in[9];
    const float* box_b  = (const float*)d_in[10];
    const float* clsp_w = (const float*)d_in[11];
    const float* clsp_b = (const float*)d_in[12];
    const float* boxp_w = (const float*)d_in[13];
    const float* boxp_b = (const float*)d_in[14];
    const float* ctrp_w = (const float*)d_in[15];
    const float* ctrp_b = (const float*)d_in[16];
    const float* scales = (const float*)d_in[17];
    float* out = (float*)d_out;

    float *bufA, *bufB, *stats, *nsc, *nsh;
    cudaGetSymbolAddress((void**)&bufA,  g_bufA);
    cudaGetSymbolAddress((void**)&bufB,  g_bufB);
    cudaGetSymbolAddress((void**)&stats, g_stats);
    cudaGetSymbolAddress((void**)&nsc,   g_nsc);
    cudaGetSymbolAddress((void**)&nsh,   g_nsh);

    const dim3 gconv(97, 4, 4);
    const dim3 gpred(71, 1, 2);

    zero_k<<<1, 256>>>(stats);

    conv_k<true ><<<gconv, 256>>>(fp, bufA, bufA, cls_w,          box_w,          nsc, nsh, stats);
    fin_k<<<20, 256>>>(cls_g,       cls_b,       box_g,       box_b,       stats, nsc, nsh);
    conv_k<false><<<gconv, 256>>>(fp, bufA, bufB, cls_w + CW,     box_w + CW,     nsc, nsh, stats);
    fin_k<<<20, 256>>>(cls_g + 256, cls_b + 256, box_g + 256, box_b + 256, stats, nsc, nsh);
    conv_k<false><<<gconv, 256>>>(fp, bufB, bufA, cls_w + 2 * CW, box_w + 2 * CW, nsc, nsh, stats);
    fin_k<<<20, 256>>>(cls_g + 512, cls_b + 512, box_g + 512, box_b + 512, stats, nsc, nsh);
    conv_k<false><<<gconv, 256>>>(fp, bufA, bufB, cls_w + 3 * CW, box_w + 3 * CW, nsc, nsh, stats);
    fin_k<<<20, 256>>>(cls_g + 768, cls_b + 768, box_g + 768, box_b + 768, stats, nsc, nsh);

    pred_cls_k<<<gpred, 256>>>(bufB, nsc, nsh, clsp_w, clsp_b, ctrp_w, ctrp_b, out);
    pred_box_k<<<gpred, 256>>>(bufB, nsc, nsh, boxp_w, boxp_b, scales, out);
}

// round 13
// speedup vs baseline: 2.3126x; 1.0006x over previous
#include <cuda_runtime.h>
#include <math.h>

// ---------------------------------------------------------------------------
// FCOS head, fused conv v5: FFMA2 direct conv.
//  v4 -> v5: weight broadcast loads fused 4x LDS.64 -> 2x LDS.128
//  (halves weight wavefronts, the dominant L1 consumer found in R11).
// ---------------------------------------------------------------------------

#define CHN   256
#define CW    (256*256*9)
#define CICH  8
#define SIH   10
#define SIW   22
#define SPADF 28               // float row stride; 28r+5q+i distinct mod 32
#define STOT  13343

__device__ float g_bufA[4 * CHN * STOT];
__device__ float g_bufB[4 * CHN * STOT];
__device__ float g_stats[1280];   // [slot(20)][group(32)][2]
__device__ float g_nsc[5120];
__device__ float g_nsh[5120];

struct Feat5 { const float* p[5]; };

__global__ void zero_k(float* s) {
    for (int i = threadIdx.x; i < 1280; i += 256) s[i] = 0.f;
}

__device__ __forceinline__ void fma2(unsigned long long& d,
                                     unsigned long long a,
                                     unsigned long long b) {
    asm("fma.rn.f32x2 %0, %1, %2, %0;" : "+l"(d) : "l"(a), "l"(b));
}

__device__ __forceinline__ unsigned long long dup2(float v) {
    unsigned long long d;
    asm("mov.b64 %0, {%1, %1};" : "=l"(d) : "f"(v));
    return d;
}

__device__ __forceinline__ float2 up2(unsigned long long v) {
    float2 f;
    asm("mov.b64 {%0, %1}, %2;" : "=f"(f.x), "=f"(f.y) : "l"(v));
    return f;
}

// ---------------------------------------------------------------------------
// Tower conv: 256->256 3x3 SAME, all levels/towers/batches in one launch.
// grid = (97 tiles, 4 co-blocks of 64, 4 = tower*2+b), block = 256.
// Warp w owns co [co0+8w, co0+8w+8); lane = (row r 0..7, colquad q 0..3).
// ---------------------------------------------------------------------------
template<bool FIRST>
__global__ __launch_bounds__(256, 3)
void conv_k(Feat5 fp, const float* __restrict__ bin, float* __restrict__ bout,
            const float* __restrict__ wcls, const float* __restrict__ wbox,
            const float* __restrict__ nsc, const float* __restrict__ nsh,
            float* __restrict__ stats)
{
    __shared__ __align__(16) float  s_in[CICH][SIH][SPADF];
    __shared__ __align__(16) float2 s_w2[CICH][9][32];   // [ci][tap][co-pair]

    const int tid = threadIdx.x;
    const int bx = blockIdx.x;
    int l = 0;
    if (bx >= 65) l = 1;
    if (bx >= 86) l = 2;
    if (bx >= 94) l = 3;
    if (bx >= 96) l = 4;
    const int HSs[5]   = {100, 50, 25, 13, 7};
    const int TBASE[5] = {0, 65, 86, 94, 96};
    const int TXN[5]   = {5, 3, 2, 1, 1};
    const int PB[5]    = {0, 10000, 12500, 13125, 13294};
    const int H = HSs[l], W = H, HW = H * W;
    const int tX = TXN[l];
    const int t  = bx - TBASE[l];
    const int ty = t / tX, tx = t - ty * tX;
    const int y0 = ty * 8, x0 = tx * 20;

    const int b   = blockIdx.z & 1;
    const int tw  = blockIdx.z >> 1;
    const int co0 = blockIdx.y << 6;            // 64 co per block
    const int slot = (l * 2 + tw) * 2 + b;

    const float* w = (tw ? wbox : wcls);
    const size_t lvlbase = (size_t)1024 * PB[l];
    const float* inb;
    if (FIRST) inb = fp.p[l] + (size_t)b * CHN * HW;
    else       inb = bin + lvlbase + (size_t)((tw * 2 + b) * CHN) * HW;
    float* outb = bout + lvlbase + (size_t)((tw * 2 + b) * CHN) * HW;

    const float* nscb = nsc + slot * CHN;
    const float* nshb = nsh + slot * CHN;

    const int wid  = tid >> 5;
    const int lane = tid & 31;
    const int r    = lane >> 2;          // row 0..7
    const int xq5  = (lane & 3) * 5;     // col base 0,5,10,15

    // ---- fixed staging assignment: thread owns one halo pixel ----
    const int  sIY = tid / SIW;                  // 0..11 (valid < SIH)
    const int  sIX = tid - sIY * SIW;
    const bool sAct = (tid < SIH * SIW);         // 220 active
    const int  sgy = y0 - 1 + sIY, sgx = x0 - 1 + sIX;
    const bool sIn = sAct && (unsigned)sgy < (unsigned)H &&
                             (unsigned)sgx < (unsigned)W;
    const float* sPtr = inb + (size_t)sgy * W + sgx;   // valid only if sIn

    unsigned long long acc[4][5];
#pragma unroll
    for (int i = 0; i < 4; i++)
#pragma unroll
        for (int j = 0; j < 5; j++) acc[i][j] = 0ull;

    for (int ci0 = 0; ci0 < CHN; ci0 += CICH) {
        // ---- stage inputs: 8 channels of this thread's halo pixel ----
        if (sAct) {
#pragma unroll
            for (int ci = 0; ci < CICH; ci++) {
                float v = 0.f;
                if (sIn) {
                    const int c = ci0 + ci;
                    v = sPtr[(size_t)c * HW];
                    if (!FIRST) v = fmaxf(fmaf(v, nscb[c], nshb[c]), 0.f);
                }
                s_in[ci][sIY][sIX] = v;
            }
        }
        // ---- stage weights as co-pairs ----
#pragma unroll 1
        for (int j = tid; j < CICH * 9 * 32; j += 256) {
            int cp = j & 31;
            int t2 = j >> 5;            // 0..71
            int k  = t2 % 9;
            int ci = t2 / 9;
            const float* wp = w + ((size_t)(co0 + 2 * cp) * CHN + (ci0 + ci)) * 9 + k;
            s_w2[ci][k][cp] = make_float2(wp[0], wp[CHN * 9]);
        }
        __syncthreads();

#pragma unroll 1
        for (int ci = 0; ci < CICH; ci++) {
#pragma unroll
            for (int ky = 0; ky < 3; ky++) {
                unsigned long long vv[7];
#pragma unroll
                for (int i2 = 0; i2 < 7; i2++)
                    vv[i2] = dup2(s_in[ci][r + ky][xq5 + i2]);
#pragma unroll
                for (int kx = 0; kx < 3; kx++) {
                    // 4 co-pair weights = 32B contiguous, 16B-aligned,
                    // warp-uniform -> 2x LDS.128 broadcast (was 4x LDS.64)
                    const ulonglong2* wp =
                        (const ulonglong2*)&s_w2[ci][ky * 3 + kx][wid << 2];
                    const ulonglong2 wA = wp[0];
                    const ulonglong2 wB = wp[1];
#pragma unroll
                    for (int p = 0; p < 5; p++) {
                        const unsigned long long v = vv[kx + p];
                        fma2(acc[0][p], wA.x, v);
                        fma2(acc[1][p], wA.y, v);
                        fma2(acc[2][p], wB.x, v);
                        fma2(acc[3][p], wB.y, v);
                    }
                }
            }
        }
        __syncthreads();
    }

    // ---- epilogue: unpack, store, per-warp group stats ----
    float s = 0.f, ss = 0.f;
    const int coT = co0 + (wid << 3);    // thread's 8 channels = 1 GN group
    const int gy  = y0 + r;
    const bool okrow = (gy < H);
#pragma unroll
    for (int p = 0; p < 5; p++) {
        const int gx = x0 + xq5 + p;
        if (okrow && gx < W) {
            const size_t off = (size_t)gy * W + gx;
#pragma unroll
            for (int cp = 0; cp < 4; cp++) {
                float2 f = up2(acc[cp][p]);
                outb[(size_t)(coT + 2 * cp)     * HW + off] = f.x;
                outb[(size_t)(coT + 2 * cp + 1) * HW + off] = f.y;
                s += f.x + f.y;
                ss = fmaf(f.x, f.x, ss);
                ss = fmaf(f.y, f.y, ss);
            }
        }
    }
#pragma unroll
    for (int o = 16; o > 0; o >>= 1) {
        s  += __shfl_xor_sync(0xffffffffu, s,  o);
        ss += __shfl_xor_sync(0xffffffffu, ss, o);
    }
    if (lane == 0) {
        const int g = (co0 >> 3) + wid;
        atomicAdd(&stats[slot * 64 + g * 2],     s);
        atomicAdd(&stats[slot * 64 + g * 2 + 1], ss);
    }
}

// ---------------------------------------------------------------------------
// finalize GN (unchanged)
// ---------------------------------------------------------------------------
__global__ void fin_k(const float* __restrict__ cg, const float* __restrict__ cb,
                      const float* __restrict__ bg, const float* __restrict__ bb,
                      float* __restrict__ stats,
                      float* __restrict__ nsc, float* __restrict__ nsh)
{
    const int slot = blockIdx.x;
    const int l  = slot >> 2;
    const int tw = (slot >> 1) & 1;
    const int c  = threadIdx.x;
    const int g  = c >> 3;
    const int HSs[5] = {100, 50, 25, 13, 7};
    const float invcnt = 1.f / (8.f * HSs[l] * HSs[l]);

    const float sum = stats[slot * 64 + g * 2];
    const float sq  = stats[slot * 64 + g * 2 + 1];
    const float mean = sum * invcnt;
    const float var  = fmaf(-mean, mean, sq * invcnt);
    const float rstd = rsqrtf(var + 1e-5f);
    const float* gam = tw ? bg : cg;
    const float* bet = tw ? bb : cb;
    const float sc = gam[c] * rstd;
    nsc[slot * 256 + c] = sc;
    nsh[slot * 256 + c] = fmaf(-mean, sc, bet[c]);
    __syncthreads();
    if (c < 64) stats[slot * 64 + c] = 0.f;
}

// ---------------------------------------------------------------------------
// cls_pred(20) + ctr_pred(1) fused (unchanged, passing)
// ---------------------------------------------------------------------------
__global__ __launch_bounds__(256)
void pred_cls_k(const float* __restrict__ bin,
                const float* __restrict__ nsc, const float* __restrict__ nsh,
                const float* __restrict__ clsw, const float* __restrict__ clsb,
                const float* __restrict__ ctrw, const float* __restrict__ ctrb,
                float* __restrict__ out)
{
    __shared__ __align__(16) float s_in[CICH][18][19];
    __shared__ __align__(16) float s_wk[CICH][9][24];

    const int tid = threadIdx.x;
    const int bx = blockIdx.x;
    int l = 0;
    if (bx >= 49) l = 1;
    if (bx >= 65) l = 2;
    if (bx >= 69) l = 3;
    if (bx >= 70) l = 4;
    const int HSs[5]   = {100, 50, 25, 13, 7};
    const int TBASE[5] = {0, 49, 65, 69, 70};
    const int TXN[5]   = {7, 4, 2, 1, 1};
    const int PB[5]    = {0, 10000, 12500, 13125, 13294};
    const int H = HSs[l], W = H, HW = H * W;
    const int t = bx - TBASE[l];
    const int tX = TXN[l];
    const int ty = t / tX, tx = t - ty * tX;
    const int y0 = ty * 16, x0 = tx * 16;
    const int b = blockIdx.z;
    const int slot = (l * 2 + 0) * 2 + b;
    const int ly = tid >> 4, lx = tid & 15;

    const float* inb  = bin + (size_t)1024 * PB[l] + (size_t)((0 * 2 + b) * CHN) * HW;
    const float* nscb = nsc + slot * CHN;
    const float* nshb = nsh + slot * CHN;

    float acc[24];
#pragma unroll
    for (int k = 0; k < 24; k++) acc[k] = 0.f;
#pragma unroll
    for (int k = 0; k < 20; k++) acc[k] = clsb[k];
    acc[20] = ctrb[0];

    for (int ci0 = 0; ci0 < CHN; ci0 += CICH) {
#pragma unroll 1
        for (int j = tid; j < CICH * 18 * 18; j += 256) {
            int ci = j / 324;
            int r2 = j - ci * 324;
            int iy = r2 / 18, ix = r2 - iy * 18;
            int gy = y0 - 1 + iy, gx = x0 - 1 + ix;
            float v = 0.f;
            if ((unsigned)gy < (unsigned)H && (unsigned)gx < (unsigned)W) {
                int c = ci0 + ci;
                v = fmaxf(fmaf(inb[(size_t)c * HW + gy * W + gx], nscb[c], nshb[c]), 0.f);
            }
            s_in[ci][iy][ix] = v;
        }
#pragma unroll 1
        for (int j = tid; j < CICH * 216; j += 256) {
            int ci = j / 216;
            int r2 = j - ci * 216;
            int kk = r2 / 24;
            int k  = r2 - kk * 24;
            int c  = ci0 + ci;
            float v = 0.f;
            if (k < 20)       v = clsw[((size_t)k * CHN + c) * 9 + kk];
            else if (k == 20) v = ctrw[(size_t)c * 9 + kk];
            s_wk[ci][kk][k] = v;
        }
        __syncthreads();
#pragma unroll 2
        for (int ci = 0; ci < CICH; ci++) {
#pragma unroll
            for (int ky = 0; ky < 3; ky++)
#pragma unroll
                for (int kx = 0; kx < 3; kx++) {
                    const float v = s_in[ci][ly + ky][lx + kx];
#pragma unroll
                    for (int kq = 0; kq < 6; kq++) {
                        const float4 wv = *(const float4*)&s_wk[ci][ky * 3 + kx][kq << 2];
                        acc[kq * 4 + 0] = fmaf(v, wv.x, acc[kq * 4 + 0]);
                        acc[kq * 4 + 1] = fmaf(v, wv.y, acc[kq * 4 + 1]);
                        acc[kq * 4 + 2] = fmaf(v, wv.z, acc[kq * 4 + 2]);
                        acc[kq * 4 + 3] = fmaf(v, wv.w, acc[kq * 4 + 3]);
                    }
                }
        }
        __syncthreads();
    }

    const int gy = y0 + ly, gx = x0 + lx;
    if (gy < H && gx < W) {
        float* lg = out + (size_t)40 * PB[l];
#pragma unroll
        for (int k = 0; k < 20; k++)
            lg[((size_t)(b * 20 + k)) * HW + gy * W + gx] = acc[k];
        out[(size_t)48 * STOT + 2 * PB[l] + (size_t)b * HW + gy * W + gx] = acc[20];
    }
}

// ---------------------------------------------------------------------------
// box_pred(4) with exp(v*scale) (unchanged, passing)
// ---------------------------------------------------------------------------
__global__ __launch_bounds__(256)
void pred_box_k(const float* __restrict__ bin,
                const float* __restrict__ nsc, const float* __restrict__ nsh,
                const float* __restrict__ boxw, const float* __restrict__ boxb,
                const float* __restrict__ scales, float* __restrict__ out)
{
    __shared__ __align__(16) float s_in[CICH][18][19];
    __shared__ __align__(16) float s_wk[CICH][9][4];

    const int tid = threadIdx.x;
    const int bx = blockIdx.x;
    int l = 0;
    if (bx >= 49) l = 1;
    if (bx >= 65) l = 2;
    if (bx >= 69) l = 3;
    if (bx >= 70) l = 4;
    const int HSs[5]   = {100, 50, 25, 13, 7};
    const int TBASE[5] = {0, 49, 65, 69, 70};
    const int TXN[5]   = {7, 4, 2, 1, 1};
    const int PB[5]    = {0, 10000, 12500, 13125, 13294};
    const int H = HSs[l], W = H, HW = H * W;
    const int t = bx - TBASE[l];
    const int tX = TXN[l];
    const int ty = t / tX, tx = t - ty * tX;
    const int y0 = ty * 16, x0 = tx * 16;
    const int b = blockIdx.z;
    const int slot = (l * 2 + 1) * 2 + b;
    const int ly = tid >> 4, lx = tid & 15;

    const float* inb  = bin + (size_t)1024 * PB[l] + (size_t)((1 * 2 + b) * CHN) * HW;
    const float* nscb = nsc + slot * CHN;
    const float* nshb = nsh + slot * CHN;

    float acc[4];
#pragma unroll
    for (int k = 0; k < 4; k++) acc[k] = boxb[k];

    for (int ci0 = 0; ci0 < CHN; ci0 += CICH) {
#pragma unroll 1
        for (int j = tid; j < CICH * 18 * 18; j += 256) {
            int ci = j / 324;
            int r2 = j - ci * 324;
            int iy = r2 / 18, ix = r2 - iy * 18;
            int gy = y0 - 1 + iy, gx = x0 - 1 + ix;
            float v = 0.f;
            if ((unsigned)gy < (unsigned)H && (unsigned)gx < (unsigned)W) {
                int c = ci0 + ci;
                v = fmaxf(fmaf(inb[(size_t)c * HW + gy * W + gx], nscb[c], nshb[c]), 0.f);
            }
            s_in[ci][iy][ix] = v;
        }
#pragma unroll 1
        for (int j = tid; j < CICH * 36; j += 256) {
            int ci = j / 36;
            int r2 = j - ci * 36;
            int kk = r2 >> 2;
            int k  = r2 & 3;
            s_wk[ci][kk][k] = boxw[((size_t)k * CHN + ci0 + ci) * 9 + kk];
        }
        __syncthreads();
#pragma unroll 2
        for (int ci = 0; ci < CICH; ci++) {
#pragma unroll
            for (int ky = 0; ky < 3; ky++)
#pragma unroll
                for (int kx = 0; kx < 3; kx++) {
                    const float v = s_in[ci][ly + ky][lx + kx];
                    const float4 wv = *(const float4*)&s_wk[ci][ky * 3 + kx][0];
                    acc[0] = fmaf(v, wv.x, acc[0]);
                    acc[1] = fmaf(v, wv.y, acc[1]);
                    acc[2] = fmaf(v, wv.z, acc[2]);
                    acc[3] = fmaf(v, wv.w, acc[3]);
                }
        }
        __syncthreads();
    }

    const int gy = y0 + ly, gx = x0 + lx;
    if (gy < H && gx < W) {
        const float scl = scales[l];
        float* bo = out + (size_t)40 * STOT + 8 * PB[l];
#pragma unroll
        for (int k = 0; k < 4; k++)
            bo[((size_t)(b * 4 + k)) * HW + gy * W + gx] = expf(acc[k] * scl);
    }
}

// ---------------------------------------------------------------------------
extern "C" void kernel_launch(void* const* d_in, const int* in_sizes, int n_in,
                              void* d_out, int out_size)
{
    (void)in_sizes; (void)n_in; (void)out_size;

    Feat5 fp;
    for (int i = 0; i < 5; i++) fp.p[i] = (const float*)d_in[i];
    const float* cls_w  = (const float*)d_in[5];
    const float* cls_g  = (const float*)d_in[6];
    const float* cls_b  = (const float*)d_in[7];
    const float* box_w  = (const float*)d_in[8];
    const float* box_g  = (const float*)d_in[9];
    const float* box_b  = (const float*)d_in[10];
    const float* clsp_w = (const float*)d_in[11];
    const float* clsp_b = (const float*)d_in[12];
    const float* boxp_w = (const float*)d_in[13];
    const float* boxp_b = (const float*)d_in[14];
    const float* ctrp_w = (const float*)d_in[15];
    const float* ctrp_b = (const float*)d_in[16];
    const float* scales = (const float*)d_in[17];
    float* out = (float*)d_out;

    float *bufA, *bufB, *stats, *nsc, *nsh;
    cudaGetSymbolAddress((void**)&bufA,  g_bufA);
    cudaGetSymbolAddress((void**)&bufB,  g_bufB);
    cudaGetSymbolAddress((void**)&stats, g_stats);
    cudaGetSymbolAddress((void**)&nsc,   g_nsc);
    cudaGetSymbolAddress((void**)&nsh,   g_nsh);

    const dim3 gconv(97, 4, 4);
    const dim3 gpred(71, 1, 2);

    zero_k<<<1, 256>>>(stats);

    conv_k<true ><<<gconv, 256>>>(fp, bufA, bufA, cls_w,          box_w,          nsc, nsh, stats);
    fin_k<<<20, 256>>>(cls_g,       cls_b,       box_g,       box_b,       stats, nsc, nsh);
    conv_k<false><<<gconv, 256>>>(fp, bufA, bufB, cls_w + CW,     box_w + CW,     nsc, nsh, stats);
    fin_k<<<20, 256>>>(cls_g + 256, cls_b + 256, box_g + 256, box_b + 256, stats, nsc, nsh);
    conv_k<false><<<gconv, 256>>>(fp, bufB, bufA, cls_w + 2 * CW, box_w + 2 * CW, nsc, nsh, stats);
    fin_k<<<20, 256>>>(cls_g + 512, cls_b + 512, box_g + 512, box_b + 512, stats, nsc, nsh);
    conv_k<false><<<gconv, 256>>>(fp, bufA, bufB, cls_w + 3 * CW, box_w + 3 * CW, nsc, nsh, stats);
    fin_k<<<20, 256>>>(cls_g + 768, cls_b + 768, box_g + 768, box_b + 768, stats, nsc, nsh);

    pred_cls_k<<<gpred, 256>>>(bufB, nsc, nsh, clsp_w, clsp_b, ctrp_w, ctrp_b, out);
    pred_box_k<<<gpred, 256>>>(bufB, nsc, nsh, boxp_w, boxp_b, scales, out);
}

// round 14
// speedup vs baseline: 3.0231x; 1.3072x over previous
#include <cuda_runtime.h>
#include <math.h>

// ---------------------------------------------------------------------------
// FCOS head, fused conv v6: FFMA2 direct conv + pre-reordered weights.
//  v5 -> v6: weights reordered once per launch into the exact smem layout
//  ([wset][co-block][chunk][ci][k][co-pair] float2). Conv weight staging is
//  now a flat coalesced float4 copy (was 4608 uncoalesced LDG wf/block/chunk).
// ---------------------------------------------------------------------------

#define CHN   256
#define CW    (256*256*9)
#define CICH  8
#define SIH   10
#define SIW   22
#define SPADF 28               // float row stride; 28r+5q+i distinct mod 32
#define STOT  13343

__device__ float  g_bufA[4 * CHN * STOT];
__device__ float  g_bufB[4 * CHN * STOT];
__device__ float2 g_wre[8 * 4 * 32 * 2304];   // 18.9MB reordered weights
__device__ float  g_stats[1280];
__device__ float  g_nsc[5120];
__device__ float  g_nsh[5120];

struct Feat5 { const float* p[5]; };

__global__ void zero_k(float* s) {
    for (int i = threadIdx.x; i < 1280; i += 256) s[i] = 0.f;
}

// ---------------------------------------------------------------------------
// Weight reorder: wre[wset][cb][chunk][ci][k][cp] = (w[2cp], w[2cp+1])
// wset = layer*2 + tower. 2359296 float2 elements, one per thread.
// ---------------------------------------------------------------------------
__global__ void wre_k(const float* __restrict__ cls_w,
                      const float* __restrict__ box_w,
                      float2* __restrict__ wre)
{
    const int idx = blockIdx.x * 256 + threadIdx.x;   // grid sized exactly
    const int wset = idx / 294912;            // 4*32*2304
    int r  = idx - wset * 294912;
    const int cb = r / 73728;  r -= cb * 73728;   // 32*2304
    const int ch = r / 2304;   r -= ch * 2304;
    const int ci = r / 288;    r -= ci * 288;
    const int k  = r / 32;
    const int cp = r - k * 32;

    const float* w = ((wset & 1) ? box_w : cls_w) + (wset >> 1) * CW;
    const int co = cb * 64 + 2 * cp;
    const int c  = ch * 8 + ci;
    wre[idx] = make_float2(w[((size_t)co * CHN + c) * 9 + k],
                           w[((size_t)(co + 1) * CHN + c) * 9 + k]);
}

__device__ __forceinline__ void fma2(unsigned long long& d,
                                     unsigned long long a,
                                     unsigned long long b) {
    asm("fma.rn.f32x2 %0, %1, %2, %0;" : "+l"(d) : "l"(a), "l"(b));
}

__device__ __forceinline__ unsigned long long dup2(float v) {
    unsigned long long d;
    asm("mov.b64 %0, {%1, %1};" : "=l"(d) : "f"(v));
    return d;
}

__device__ __forceinline__ float2 up2(unsigned long long v) {
    float2 f;
    asm("mov.b64 {%0, %1}, %2;" : "=f"(f.x), "=f"(f.y) : "l"(v));
    return f;
}

// ---------------------------------------------------------------------------
// Tower conv: 256->256 3x3 SAME, all levels/towers/batches in one launch.
// grid = (97 tiles, 4 co-blocks of 64, 4 = tower*2+b), block = 256.
// ---------------------------------------------------------------------------
template<bool FIRST>
__global__ __launch_bounds__(256, 3)
void conv_k(Feat5 fp, const float* __restrict__ bin, float* __restrict__ bout,
            const float2* __restrict__ wre, int layer,
            const float* __restrict__ nsc, const float* __restrict__ nsh,
            float* __restrict__ stats)
{
    __shared__ __align__(16) float  s_in[CICH][SIH][SPADF];
    __shared__ __align__(16) float2 s_w2[CICH][9][32];   // [ci][tap][co-pair]

    const int tid = threadIdx.x;
    const int bx = blockIdx.x;
    int l = 0;
    if (bx >= 65) l = 1;
    if (bx >= 86) l = 2;
    if (bx >= 94) l = 3;
    if (bx >= 96) l = 4;
    const int HSs[5]   = {100, 50, 25, 13, 7};
    const int TBASE[5] = {0, 65, 86, 94, 96};
    const int TXN[5]   = {5, 3, 2, 1, 1};
    const int PB[5]    = {0, 10000, 12500, 13125, 13294};
    const int H = HSs[l], W = H, HW = H * W;
    const int tX = TXN[l];
    const int t  = bx - TBASE[l];
    const int ty = t / tX, tx = t - ty * tX;
    const int y0 = ty * 8, x0 = tx * 20;

    const int b   = blockIdx.z & 1;
    const int tw  = blockIdx.z >> 1;
    const int co0 = blockIdx.y << 6;            // 64 co per block
    const int slot = (l * 2 + tw) * 2 + b;

    // reordered weights for this (layer,tower,co-block)
    const float2* wrb = wre + (size_t)(((layer * 2 + tw) * 4 + blockIdx.y) * 32) * 2304;

    const size_t lvlbase = (size_t)1024 * PB[l];
    const float* inb;
    if (FIRST) inb = fp.p[l] + (size_t)b * CHN * HW;
    else       inb = bin + lvlbase + (size_t)((tw * 2 + b) * CHN) * HW;
    float* outb = bout + lvlbase + (size_t)((tw * 2 + b) * CHN) * HW;

    const float* nscb = nsc + slot * CHN;
    const float* nshb = nsh + slot * CHN;

    const int wid  = tid >> 5;
    const int lane = tid & 31;
    const int r    = lane >> 2;          // row 0..7
    const int xq5  = (lane & 3) * 5;     // col base 0,5,10,15

    // ---- fixed staging assignment: thread owns one halo pixel ----
    const int  sIY = tid / SIW;
    const int  sIX = tid - sIY * SIW;
    const bool sAct = (tid < SIH * SIW);
    const int  sgy = y0 - 1 + sIY, sgx = x0 - 1 + sIX;
    const bool sIn = sAct && (unsigned)sgy < (unsigned)H &&
                             (unsigned)sgx < (unsigned)W;
    const float* sPtr = inb + (size_t)sgy * W + sgx;

    unsigned long long acc[4][5];
#pragma unroll
    for (int i = 0; i < 4; i++)
#pragma unroll
        for (int j = 0; j < 5; j++) acc[i][j] = 0ull;

    for (int ci0 = 0; ci0 < CHN; ci0 += CICH) {
        // ---- stage inputs: 8 channels of this thread's halo pixel ----
        if (sAct) {
#pragma unroll
            for (int ci = 0; ci < CICH; ci++) {
                float v = 0.f;
                if (sIn) {
                    const int c = ci0 + ci;
                    v = sPtr[(size_t)c * HW];
                    if (!FIRST) v = fmaxf(fmaf(v, nscb[c], nshb[c]), 0.f);
                }
                s_in[ci][sIY][sIX] = v;
            }
        }
        // ---- stage weights: flat coalesced copy (1152 float4) ----
        {
            const float4* wsrc = (const float4*)(wrb + (size_t)(ci0 >> 3) * 2304);
            float4* wdst = (float4*)&s_w2[0][0][0];
#pragma unroll 1
            for (int j = tid; j < 1152; j += 256)
                wdst[j] = wsrc[j];
        }
        __syncthreads();

#pragma unroll 1
        for (int ci = 0; ci < CICH; ci++) {
#pragma unroll
            for (int ky = 0; ky < 3; ky++) {
                unsigned long long vv[7];
#pragma unroll
                for (int i2 = 0; i2 < 7; i2++)
                    vv[i2] = dup2(s_in[ci][r + ky][xq5 + i2]);
#pragma unroll
                for (int kx = 0; kx < 3; kx++) {
                    const ulonglong2* wp =
                        (const ulonglong2*)&s_w2[ci][ky * 3 + kx][wid << 2];
                    const ulonglong2 wA = wp[0];
                    const ulonglong2 wB = wp[1];
#pragma unroll
                    for (int p = 0; p < 5; p++) {
                        const unsigned long long v = vv[kx + p];
                        fma2(acc[0][p], wA.x, v);
                        fma2(acc[1][p], wA.y, v);
                        fma2(acc[2][p], wB.x, v);
                        fma2(acc[3][p], wB.y, v);
                    }
                }
            }
        }
        __syncthreads();
    }

    // ---- epilogue: unpack, store, per-warp group stats ----
    float s = 0.f, ss = 0.f;
    const int coT = co0 + (wid << 3);
    const int gy  = y0 + r;
    const bool okrow = (gy < H);
#pragma unroll
    for (int p = 0; p < 5; p++) {
        const int gx = x0 + xq5 + p;
        if (okrow && gx < W) {
            const size_t off = (size_t)gy * W + gx;
#pragma unroll
            for (int cp = 0; cp < 4; cp++) {
                float2 f = up2(acc[cp][p]);
                outb[(size_t)(coT + 2 * cp)     * HW + off] = f.x;
                outb[(size_t)(coT + 2 * cp + 1) * HW + off] = f.y;
                s += f.x + f.y;
                ss = fmaf(f.x, f.x, ss);
                ss = fmaf(f.y, f.y, ss);
            }
        }
    }
#pragma unroll
    for (int o = 16; o > 0; o >>= 1) {
        s  += __shfl_xor_sync(0xffffffffu, s,  o);
        ss += __shfl_xor_sync(0xffffffffu, ss, o);
    }
    if (lane == 0) {
        const int g = (co0 >> 3) + wid;
        atomicAdd(&stats[slot * 64 + g * 2],     s);
        atomicAdd(&stats[slot * 64 + g * 2 + 1], ss);
    }
}

// ---------------------------------------------------------------------------
// finalize GN (unchanged)
// ---------------------------------------------------------------------------
__global__ void fin_k(const float* __restrict__ cg, const float* __restrict__ cb,
                      const float* __restrict__ bg, const float* __restrict__ bb,
                      float* __restrict__ stats,
                      float* __restrict__ nsc, float* __restrict__ nsh)
{
    const int slot = blockIdx.x;
    const int l  = slot >> 2;
    const int tw = (slot >> 1) & 1;
    const int c  = threadIdx.x;
    const int g  = c >> 3;
    const int HSs[5] = {100, 50, 25, 13, 7};
    const float invcnt = 1.f / (8.f * HSs[l] * HSs[l]);

    const float sum = stats[slot * 64 + g * 2];
    const float sq  = stats[slot * 64 + g * 2 + 1];
    const float mean = sum * invcnt;
    const float var  = fmaf(-mean, mean, sq * invcnt);
    const float rstd = rsqrtf(var + 1e-5f);
    const float* gam = tw ? bg : cg;
    const float* bet = tw ? bb : cb;
    const float sc = gam[c] * rstd;
    nsc[slot * 256 + c] = sc;
    nsh[slot * 256 + c] = fmaf(-mean, sc, bet[c]);
    __syncthreads();
    if (c < 64) stats[slot * 64 + c] = 0.f;
}

// ---------------------------------------------------------------------------
// cls_pred(20) + ctr_pred(1) fused (unchanged, passing)
// ---------------------------------------------------------------------------
__global__ __launch_bounds__(256)
void pred_cls_k(const float* __restrict__ bin,
                const float* __restrict__ nsc, const float* __restrict__ nsh,
                const float* __restrict__ clsw, const float* __restrict__ clsb,
                const float* __restrict__ ctrw, const float* __restrict__ ctrb,
                float* __restrict__ out)
{
    __shared__ __align__(16) float s_in[CICH][18][19];
    __shared__ __align__(16) float s_wk[CICH][9][24];

    const int tid = threadIdx.x;
    const int bx = blockIdx.x;
    int l = 0;
    if (bx >= 49) l = 1;
    if (bx >= 65) l = 2;
    if (bx >= 69) l = 3;
    if (bx >= 70) l = 4;
    const int HSs[5]   = {100, 50, 25, 13, 7};
    const int TBASE[5] = {0, 49, 65, 69, 70};
    const int TXN[5]   = {7, 4, 2, 1, 1};
    const int PB[5]    = {0, 10000, 12500, 13125, 13294};
    const int H = HSs[l], W = H, HW = H * W;
    const int t = bx - TBASE[l];
    const int tX = TXN[l];
    const int ty = t / tX, tx = t - ty * tX;
    const int y0 = ty * 16, x0 = tx * 16;
    const int b = blockIdx.z;
    const int slot = (l * 2 + 0) * 2 + b;
    const int ly = tid >> 4, lx = tid & 15;

    const float* inb  = bin + (size_t)1024 * PB[l] + (size_t)((0 * 2 + b) * CHN) * HW;
    const float* nscb = nsc + slot * CHN;
    const float* nshb = nsh + slot * CHN;

    float acc[24];
#pragma unroll
    for (int k = 0; k < 24; k++) acc[k] = 0.f;
#pragma unroll
    for (int k = 0; k < 20; k++) acc[k] = clsb[k];
    acc[20] = ctrb[0];

    for (int ci0 = 0; ci0 < CHN; ci0 += CICH) {
#pragma unroll 1
        for (int j = tid; j < CICH * 18 * 18; j += 256) {
            int ci = j / 324;
            int r2 = j - ci * 324;
            int iy = r2 / 18, ix = r2 - iy * 18;
            int gy = y0 - 1 + iy, gx = x0 - 1 + ix;
            float v = 0.f;
            if ((unsigned)gy < (unsigned)H && (unsigned)gx < (unsigned)W) {
                int c = ci0 + ci;
                v = fmaxf(fmaf(inb[(size_t)c * HW + gy * W + gx], nscb[c], nshb[c]), 0.f);
            }
            s_in[ci][iy][ix] = v;
        }
#pragma unroll 1
        for (int j = tid; j < CICH * 216; j += 256) {
            int ci = j / 216;
            int r2 = j - ci * 216;
            int kk = r2 / 24;
            int k  = r2 - kk * 24;
            int c  = ci0 + ci;
            float v = 0.f;
            if (k < 20)       v = clsw[((size_t)k * CHN + c) * 9 + kk];
            else if (k == 20) v = ctrw[(size_t)c * 9 + kk];
            s_wk[ci][kk][k] = v;
        }
        __syncthreads();
#pragma unroll 2
        for (int ci = 0; ci < CICH; ci++) {
#pragma unroll
            for (int ky = 0; ky < 3; ky++)
#pragma unroll
                for (int kx = 0; kx < 3; kx++) {
                    const float v = s_in[ci][ly + ky][lx + kx];
#pragma unroll
                    for (int kq = 0; kq < 6; kq++) {
                        const float4 wv = *(const float4*)&s_wk[ci][ky * 3 + kx][kq << 2];
                        acc[kq * 4 + 0] = fmaf(v, wv.x, acc[kq * 4 + 0]);
                        acc[kq * 4 + 1] = fmaf(v, wv.y, acc[kq * 4 + 1]);
                        acc[kq * 4 + 2] = fmaf(v, wv.z, acc[kq * 4 + 2]);
                        acc[kq * 4 + 3] = fmaf(v, wv.w, acc[kq * 4 + 3]);
                    }
                }
        }
        __syncthreads();
    }

    const int gy = y0 + ly, gx = x0 + lx;
    if (gy < H && gx < W) {
        float* lg = out + (size_t)40 * PB[l];
#pragma unroll
        for (int k = 0; k < 20; k++)
            lg[((size_t)(b * 20 + k)) * HW + gy * W + gx] = acc[k];
        out[(size_t)48 * STOT + 2 * PB[l] + (size_t)b * HW + gy * W + gx] = acc[20];
    }
}

// ---------------------------------------------------------------------------
// box_pred(4) with exp(v*scale) (unchanged, passing)
// ---------------------------------------------------------------------------
__global__ __launch_bounds__(256)
void pred_box_k(const float* __restrict__ bin,
                const float* __restrict__ nsc, const float* __restrict__ nsh,
                const float* __restrict__ boxw, const float* __restrict__ boxb,
                const float* __restrict__ scales, float* __restrict__ out)
{
    __shared__ __align__(16) float s_in[CICH][18][19];
    __shared__ __align__(16) float s_wk[CICH][9][4];

    const int tid = threadIdx.x;
    const int bx = blockIdx.x;
    int l = 0;
    if (bx >= 49) l = 1;
    if (bx >= 65) l = 2;
    if (bx >= 69) l = 3;
    if (bx >= 70) l = 4;
    const int HSs[5]   = {100, 50, 25, 13, 7};
    const int TBASE[5] = {0, 49, 65, 69, 70};
    const int TXN[5]   = {7, 4, 2, 1, 1};
    const int PB[5]    = {0, 10000, 12500, 13125, 13294};
    const int H = HSs[l], W = H, HW = H * W;
    const int t = bx - TBASE[l];
    const int tX = TXN[l];
    const int ty = t / tX, tx = t - ty * tX;
    const int y0 = ty * 16, x0 = tx * 16;
    const int b = blockIdx.z;
    const int slot = (l * 2 + 1) * 2 + b;
    const int ly = tid >> 4, lx = tid & 15;

    const float* inb  = bin + (size_t)1024 * PB[l] + (size_t)((1 * 2 + b) * CHN) * HW;
    const float* nscb = nsc + slot * CHN;
    const float* nshb = nsh + slot * CHN;

    float acc[4];
#pragma unroll
    for (int k = 0; k < 4; k++) acc[k] = boxb[k];

    for (int ci0 = 0; ci0 < CHN; ci0 += CICH) {
#pragma unroll 1
        for (int j = tid; j < CICH * 18 * 18; j += 256) {
            int ci = j / 324;
            int r2 = j - ci * 324;
            int iy = r2 / 18, ix = r2 - iy * 18;
            int gy = y0 - 1 + iy, gx = x0 - 1 + ix;
            float v = 0.f;
            if ((unsigned)gy < (unsigned)H && (unsigned)gx < (unsigned)W) {
                int c = ci0 + ci;
                v = fmaxf(fmaf(inb[(size_t)c * HW + gy * W + gx], nscb[c], nshb[c]), 0.f);
            }
            s_in[ci][iy][ix] = v;
        }
#pragma unroll 1
        for (int j = tid; j < CICH * 36; j += 256) {
            int ci = j / 36;
            int r2 = j - ci * 36;
            int kk = r2 >> 2;
            int k  = r2 & 3;
            s_wk[ci][kk][k] = boxw[((size_t)k * CHN + ci0 + ci) * 9 + kk];
        }
        __syncthreads();
#pragma unroll 2
        for (int ci = 0; ci < CICH; ci++) {
#pragma unroll
            for (int ky = 0; ky < 3; ky++)
#pragma unroll
                for (int kx = 0; kx < 3; kx++) {
                    const float v = s_in[ci][ly + ky][lx + kx];
                    const float4 wv = *(const float4*)&s_wk[ci][ky * 3 + kx][0];
                    acc[0] = fmaf(v, wv.x, acc[0]);
                    acc[1] = fmaf(v, wv.y, acc[1]);
                    acc[2] = fmaf(v, wv.z, acc[2]);
                    acc[3] = fmaf(v, wv.w, acc[3]);
                }
        }
        __syncthreads();
    }

    const int gy = y0 + ly, gx = x0 + lx;
    if (gy < H && gx < W) {
        const float scl = scales[l];
        float* bo = out + (size_t)40 * STOT + 8 * PB[l];
#pragma unroll
        for (int k = 0; k < 4; k++)
            bo[((size_t)(b * 4 + k)) * HW + gy * W + gx] = expf(acc[k] * scl);
    }
}

// ---------------------------------------------------------------------------
extern "C" void kernel_launch(void* const* d_in, const int* in_sizes, int n_in,
                              void* d_out, int out_size)
{
    (void)in_sizes; (void)n_in; (void)out_size;

    Feat5 fp;
    for (int i = 0; i < 5; i++) fp.p[i] = (const float*)d_in[i];
    const float* cls_w  = (const float*)d_in[5];
    const float* cls_g  = (const float*)d_in[6];
    const float* cls_b  = (const float*)d_in[7];
    const float* box_w  = (const float*)d_in[8];
    const float* box_g  = (const float*)d_in[9];
    const float* box_b  = (const float*)d_in[10];
    const float* clsp_w = (const float*)d_in[11];
    const float* clsp_b = (const float*)d_in[12];
    const float* boxp_w = (const float*)d_in[13];
    const float* boxp_b = (const float*)d_in[14];
    const float* ctrp_w = (const float*)d_in[15];
    const float* ctrp_b = (const float*)d_in[16];
    const float* scales = (const float*)d_in[17];
    float* out = (float*)d_out;

    float *bufA, *bufB, *stats, *nsc, *nsh;
    float2* wre;
    cudaGetSymbolAddress((void**)&bufA,  g_bufA);
    cudaGetSymbolAddress((void**)&bufB,  g_bufB);
    cudaGetSymbolAddress((void**)&wre,   g_wre);
    cudaGetSymbolAddress((void**)&stats, g_stats);
    cudaGetSymbolAddress((void**)&nsc,   g_nsc);
    cudaGetSymbolAddress((void**)&nsh,   g_nsh);

    const dim3 gconv(97, 4, 4);
    const dim3 gpred(71, 1, 2);

    zero_k<<<1, 256>>>(stats);
    wre_k<<<9216, 256>>>(cls_w, box_w, wre);   // 2359296 / 256

    conv_k<true ><<<gconv, 256>>>(fp, bufA, bufA, wre, 0, nsc, nsh, stats);
    fin_k<<<20, 256>>>(cls_g,       cls_b,       box_g,       box_b,       stats, nsc, nsh);
    conv_k<false><<<gconv, 256>>>(fp, bufA, bufB, wre, 1, nsc, nsh, stats);
    fin_k<<<20, 256>>>(cls_g + 256, cls_b + 256, box_g + 256, box_b + 256, stats, nsc, nsh);
    conv_k<false><<<gconv, 256>>>(fp, bufB, bufA, wre, 2, nsc, nsh, stats);
    fin_k<<<20, 256>>>(cls_g + 512, cls_b + 512, box_g + 512, box_b + 512, stats, nsc, nsh);
    conv_k<false><<<gconv, 256>>>(fp, bufA, bufB, wre, 3, nsc, nsh, stats);
    fin_k<<<20, 256>>>(cls_g + 768, cls_b + 768, box_g + 768, box_b + 768, stats, nsc, nsh);

    pred_cls_k<<<gpred, 256>>>(bufB, nsc, nsh, clsp_w, clsp_b, ctrp_w, ctrp_b, out);
    pred_box_k<<<gpred, 256>>>(bufB, nsc, nsh, boxp_w, boxp_b, scales, out);
}

// round 16
// speedup vs baseline: 3.1816x; 1.0524x over previous
#include <cuda_runtime.h>
#include <math.h>

// ---------------------------------------------------------------------------
// FCOS head, fused conv v7: FFMA2 direct conv + cp.async double buffering.
//  v6 -> v7:
//   - GN apply moved to its own elementwise pass (apply_k, L2-resident).
//   - conv staging = pure copies via cp.async, 2-stage ping-pong smem.
//   - pred kernels read pre-normalized buffer (no transform).
// ---------------------------------------------------------------------------

#define CHN   256
#define CW    (256*256*9)
#define CICH  8
#define SIH   10
#define SIW   22
#define SPADF 28
#define STOT  13343

#define IN_FLT   (CICH * SIH * SPADF)          // 2240 floats per stage
#define IN_BYTES (IN_FLT * 4)                  // 8960
#define W_F2     (CICH * 9 * 32)               // 2304 float2 per stage
#define W_BYTES  (W_F2 * 8)                    // 18432
#define SMEM_DYN (2 * IN_BYTES + 2 * W_BYTES)  // 54784

__device__ float  g_bufA[4 * CHN * STOT];
__device__ float  g_bufB[4 * CHN * STOT];
__device__ float2 g_wre[8 * 4 * 32 * 2304];
__device__ float  g_stats[1280];
__device__ float  g_nsc[5120];
__device__ float  g_nsh[5120];

struct Feat5 { const float* p[5]; };

__global__ void zero_k(float* s) {
    for (int i = threadIdx.x; i < 1280; i += 256) s[i] = 0.f;
}

__global__ void wre_k(const float* __restrict__ cls_w,
                      const float* __restrict__ box_w,
                      float2* __restrict__ wre)
{
    const int idx = blockIdx.x * 256 + threadIdx.x;
    const int wset = idx / 294912;
    int r  = idx - wset * 294912;
    const int cb = r / 73728;  r -= cb * 73728;
    const int ch = r / 2304;   r -= ch * 2304;
    const int ci = r / 288;    r -= ci * 288;
    const int k  = r / 32;
    const int cp = r - k * 32;

    const float* w = ((wset & 1) ? box_w : cls_w) + (wset >> 1) * CW;
    const int co = cb * 64 + 2 * cp;
    const int c  = ch * 8 + ci;
    wre[idx] = make_float2(w[((size_t)co * CHN + c) * 9 + k],
                           w[((size_t)(co + 1) * CHN + c) * 9 + k]);
}

__device__ __forceinline__ void fma2(unsigned long long& d,
                                     unsigned long long a,
                                     unsigned long long b) {
    asm("fma.rn.f32x2 %0, %1, %2, %0;" : "+l"(d) : "l"(a), "l"(b));
}
__device__ __forceinline__ unsigned long long dup2(float v) {
    unsigned long long d;
    asm("mov.b64 %0, {%1, %1};" : "=l"(d) : "f"(v));
    return d;
}
__device__ __forceinline__ float2 up2(unsigned long long v) {
    float2 f;
    asm("mov.b64 {%0, %1}, %2;" : "=f"(f.x), "=f"(f.y) : "l"(v));
    return f;
}
__device__ __forceinline__ unsigned smem_u32(const void* p) {
    return (unsigned)__cvta_generic_to_shared(p);
}
#define CP_A4(dst, src)  asm volatile("cp.async.ca.shared.global [%0],[%1],4;"  :: "r"(dst), "l"(src))
#define CP_A16(dst, src) asm volatile("cp.async.ca.shared.global [%0],[%1],16;" :: "r"(dst), "l"(src))
#define CP_COMMIT        asm volatile("cp.async.commit_group;" ::: "memory")
#define CP_WAIT1         asm volatile("cp.async.wait_group 1;" ::: "memory")
#define CP_WAIT0         asm volatile("cp.async.wait_group 0;" ::: "memory")

// ---------------------------------------------------------------------------
// Tower conv: reads PRE-NORMALIZED input, writes raw output + group stats.
// grid = (97, 4 co-blocks, 4 = tower*2+b), block = 256, dyn smem 54784B.
// ---------------------------------------------------------------------------
template<bool FIRST>
__global__ __launch_bounds__(256, 3)
void conv_k(Feat5 fp, const float* __restrict__ bin, float* __restrict__ bout,
            const float2* __restrict__ wre, int layer,
            float* __restrict__ stats)
{
    extern __shared__ __align__(16) char smem[];
    float*  s_in = (float*)smem;                       // [2][8][10][28]
    float2* s_w  = (float2*)(smem + 2 * IN_BYTES);     // [2][8][9][32]

    const int tid = threadIdx.x;
    const int bx = blockIdx.x;
    int l = 0;
    if (bx >= 65) l = 1;
    if (bx >= 86) l = 2;
    if (bx >= 94) l = 3;
    if (bx >= 96) l = 4;
    const int HSs[5]   = {100, 50, 25, 13, 7};
    const int TBASE[5] = {0, 65, 86, 94, 96};
    const int TXN[5]   = {5, 3, 2, 1, 1};
    const int PB[5]    = {0, 10000, 12500, 13125, 13294};
    const int H = HSs[l], W = H, HW = H * W;
    const int tX = TXN[l];
    const int t  = bx - TBASE[l];
    const int ty = t / tX, tx = t - ty * tX;
    const int y0 = ty * 8, x0 = tx * 20;

    const int b   = blockIdx.z & 1;
    const int tw  = blockIdx.z >> 1;
    const int co0 = blockIdx.y << 6;
    const int slot = (l * 2 + tw) * 2 + b;

    const float2* wrb = wre + (size_t)(((layer * 2 + tw) * 4 + blockIdx.y) * 32) * 2304;

    const size_t lvlbase = (size_t)1024 * PB[l];
    const float* inb;
    if (FIRST) inb = fp.p[l] + (size_t)b * CHN * HW;
    else       inb = bin + lvlbase + (size_t)((tw * 2 + b) * CHN) * HW;
    float* outb = bout + lvlbase + (size_t)((tw * 2 + b) * CHN) * HW;

    const int wid  = tid >> 5;
    const int lane = tid & 31;
    const int r    = lane >> 2;
    const int xq5  = (lane & 3) * 5;

    // ---- fixed staging slot ----
    const int  sIY = tid / SIW;
    const int  sIX = tid - sIY * SIW;
    const bool sAct = (tid < SIH * SIW);
    const int  sgy = y0 - 1 + sIY, sgx = x0 - 1 + sIX;
    const bool sIn = sAct && (unsigned)sgy < (unsigned)H &&
                             (unsigned)sgx < (unsigned)W;
    const float* sPtr = inb + (size_t)sgy * W + sgx;

    // zero OOB halo slots once (cp.async never writes them)
    if (sAct && !sIn) {
#pragma unroll
        for (int s = 0; s < 2; s++)
#pragma unroll
            for (int ci = 0; ci < CICH; ci++)
                s_in[(s * CICH + ci) * 280 + sIY * 28 + sIX] = 0.f;
    }

    const unsigned inAddr = smem_u32(s_in) + (sIY * 28 + sIX) * 4;
    const unsigned wAddr  = smem_u32(s_w);

    unsigned long long acc[4][5];
#pragma unroll
    for (int i = 0; i < 4; i++)
#pragma unroll
        for (int j = 0; j < 5; j++) acc[i][j] = 0ull;

    auto issue_stage = [&](int ch) {
        const int buf = ch & 1;
        if (sIn) {
            const float* src = sPtr + (size_t)(ch * CICH) * HW;
            const unsigned dst = inAddr + buf * IN_BYTES;
#pragma unroll
            for (int ci = 0; ci < CICH; ci++)
                CP_A4(dst + ci * 1120, src + (size_t)ci * HW);
        }
        const float4* wsrc = (const float4*)(wrb + (size_t)ch * W_F2);
        const unsigned wd = wAddr + buf * W_BYTES;
#pragma unroll 1
        for (int j = tid; j < 1152; j += 256)
            CP_A16(wd + j * 16, wsrc + j);
        CP_COMMIT;
    };

    issue_stage(0);

    for (int ch = 0; ch < 32; ch++) {
        const int buf = ch & 1;
        if (ch + 1 < 32) { issue_stage(ch + 1); CP_WAIT1; }
        else             { CP_WAIT0; }
        __syncthreads();

        const float*  siB = s_in + buf * IN_FLT;
        const float2* swB = s_w  + buf * W_F2;
#pragma unroll 1
        for (int ci = 0; ci < CICH; ci++) {
            const float*  si  = siB + ci * 280;
            const float2* swt = swB + ci * 288;
#pragma unroll
            for (int ky = 0; ky < 3; ky++) {
                unsigned long long vv[7];
#pragma unroll
                for (int i2 = 0; i2 < 7; i2++)
                    vv[i2] = dup2(si[(r + ky) * 28 + xq5 + i2]);
#pragma unroll
                for (int kx = 0; kx < 3; kx++) {
                    const ulonglong2* wp =
                        (const ulonglong2*)(swt + (ky * 3 + kx) * 32 + (wid << 2));
                    const ulonglong2 wA = wp[0];
                    const ulonglong2 wB = wp[1];
#pragma unroll
                    for (int p = 0; p < 5; p++) {
                        const unsigned long long v = vv[kx + p];
                        fma2(acc[0][p], wA.x, v);
                        fma2(acc[1][p], wA.y, v);
                        fma2(acc[2][p], wB.x, v);
                        fma2(acc[3][p], wB.y, v);
                    }
                }
            }
        }
        __syncthreads();
    }

    // ---- epilogue: store raw + per-warp group stats ----
    float s = 0.f, ss = 0.f;
    const int coT = co0 + (wid << 3);
    const int gy  = y0 + r;
    const bool okrow = (gy < H);
#pragma unroll
    for (int p = 0; p < 5; p++) {
        const int gx = x0 + xq5 + p;
        if (okrow && gx < W) {
            const size_t off = (size_t)gy * W + gx;
#pragma unroll
            for (int cp = 0; cp < 4; cp++) {
                float2 f = up2(acc[cp][p]);
                outb[(size_t)(coT + 2 * cp)     * HW + off] = f.x;
                outb[(size_t)(coT + 2 * cp + 1) * HW + off] = f.y;
                s += f.x + f.y;
                ss = fmaf(f.x, f.x, ss);
                ss = fmaf(f.y, f.y, ss);
            }
        }
    }
#pragma unroll
    for (int o = 16; o > 0; o >>= 1) {
        s  += __shfl_xor_sync(0xffffffffu, s,  o);
        ss += __shfl_xor_sync(0xffffffffu, ss, o);
    }
    if (lane == 0) {
        const int g = (co0 >> 3) + wid;
        atomicAdd(&stats[slot * 64 + g * 2],     s);
        atomicAdd(&stats[slot * 64 + g * 2 + 1], ss);
    }
}

// ---------------------------------------------------------------------------
// finalize GN (unchanged)
// ---------------------------------------------------------------------------
__global__ void fin_k(const float* __restrict__ cg, const float* __restrict__ cb,
                      const float* __restrict__ bg, const float* __restrict__ bb,
                      float* __restrict__ stats,
                      float* __restrict__ nsc, float* __restrict__ nsh)
{
    const int slot = blockIdx.x;
    const int l  = slot >> 2;
    const int tw = (slot >> 1) & 1;
    const int c  = threadIdx.x;
    const int g  = c >> 3;
    const int HSs[5] = {100, 50, 25, 13, 7};
    const float invcnt = 1.f / (8.f * HSs[l] * HSs[l]);

    const float sum = stats[slot * 64 + g * 2];
    const float sq  = stats[slot * 64 + g * 2 + 1];
    const float mean = sum * invcnt;
    const float var  = fmaf(-mean, mean, sq * invcnt);
    const float rstd = rsqrtf(var + 1e-5f);
    const float* gam = tw ? bg : cg;
    const float* bet = tw ? bb : cb;
    const float sc = gam[c] * rstd;
    nsc[slot * 256 + c] = sc;
    nsh[slot * 256 + c] = fmaf(-mean, sc, bet[c]);
    __syncthreads();
    if (c < 64) stats[slot * 64 + c] = 0.f;
}

// ---------------------------------------------------------------------------
// GN apply: dst = relu(src * nsc + nsh), whole tensor (L2-resident).
// flat layout [level][tw*2+b][c][hw]; nsc index = l*1024 + cg.
// ---------------------------------------------------------------------------
__global__ __launch_bounds__(256)
void apply_k(const float* __restrict__ src, float* __restrict__ dst,
             const float* __restrict__ nsc, const float* __restrict__ nsh)
{
    const int f = blockIdx.x * 256 + threadIdx.x;
    const int N0 = 10240000, N1 = 12800000, N2 = 13440000, N3 = 13613056,
              N4 = 13663232;
    if (f >= N4) return;
    int nidx;
    if (f < N0)      { nidx =        (f)      / 10000; }
    else if (f < N1) { nidx = 1024 + (f - N0) / 2500;  }
    else if (f < N2) { nidx = 2048 + (f - N1) / 625;   }
    else if (f < N3) { nidx = 3072 + (f - N2) / 169;   }
    else             { nidx = 4096 + (f - N3) / 49;    }
    dst[f] = fmaxf(fmaf(src[f], nsc[nidx], nsh[nidx]), 0.f);
}

// ---------------------------------------------------------------------------
// cls_pred(20) + ctr_pred(1): reads pre-normalized buffer.
// ---------------------------------------------------------------------------
__global__ __launch_bounds__(256)
void pred_cls_k(const float* __restrict__ bin,
                const float* __restrict__ clsw, const float* __restrict__ clsb,
                const float* __restrict__ ctrw, const float* __restrict__ ctrb,
                float* __restrict__ out)
{
    __shared__ __align__(16) float s_in[CICH][18][19];
    __shared__ __align__(16) float s_wk[CICH][9][24];

    const int tid = threadIdx.x;
    const int bx = blockIdx.x;
    int l = 0;
    if (bx >= 49) l = 1;
    if (bx >= 65) l = 2;
    if (bx >= 69) l = 3;
    if (bx >= 70) l = 4;
    const int HSs[5]   = {100, 50, 25, 13, 7};
    const int TBASE[5] = {0, 49, 65, 69, 70};
    const int TXN[5]   = {7, 4, 2, 1, 1};
    const int PB[5]    = {0, 10000, 12500, 13125, 13294};
    const int H = HSs[l], W = H, HW = H * W;
    const int t = bx - TBASE[l];
    const int tX = TXN[l];
    const int ty = t / tX, tx = t - ty * tX;
    const int y0 = ty * 16, x0 = tx * 16;
    const int b = blockIdx.z;
    const int ly = tid >> 4, lx = tid & 15;

    const float* inb = bin + (size_t)1024 * PB[l] + (size_t)((0 * 2 + b) * CHN) * HW;

    float acc[24];
#pragma unroll
    for (int k = 0; k < 24; k++) acc[k] = 0.f;
#pragma unroll
    for (int k = 0; k < 20; k++) acc[k] = clsb[k];
    acc[20] = ctrb[0];

    for (int ci0 = 0; ci0 < CHN; ci0 += CICH) {
#pragma unroll 1
        for (int j = tid; j < CICH * 18 * 18; j += 256) {
            int ci = j / 324;
            int r2 = j - ci * 324;
            int iy = r2 / 18, ix = r2 - iy * 18;
            int gy = y0 - 1 + iy, gx = x0 - 1 + ix;
            float v = 0.f;
            if ((unsigned)gy < (unsigned)H && (unsigned)gx < (unsigned)W)
                v = inb[(size_t)(ci0 + ci) * HW + gy * W + gx];
            s_in[ci][iy][ix] = v;
        }
#pragma unroll 1
        for (int j = tid; j < CICH * 216; j += 256) {
            int ci = j / 216;
            int r2 = j - ci * 216;
            int kk = r2 / 24;
            int k  = r2 - kk * 24;
            int c  = ci0 + ci;
            float v = 0.f;
            if (k < 20)       v = clsw[((size_t)k * CHN + c) * 9 + kk];
            else if (k == 20) v = ctrw[(size_t)c * 9 + kk];
            s_wk[ci][kk][k] = v;
        }
        __syncthreads();
#pragma unroll 2
        for (int ci = 0; ci < CICH; ci++) {
#pragma unroll
            for (int ky = 0; ky < 3; ky++)
#pragma unroll
                for (int kx = 0; kx < 3; kx++) {
                    const float v = s_in[ci][ly + ky][lx + kx];
#pragma unroll
                    for (int kq = 0; kq < 6; kq++) {
                        const float4 wv = *(const float4*)&s_wk[ci][ky * 3 + kx][kq << 2];
                        acc[kq * 4 + 0] = fmaf(v, wv.x, acc[kq * 4 + 0]);
                        acc[kq * 4 + 1] = fmaf(v, wv.y, acc[kq * 4 + 1]);
                        acc[kq * 4 + 2] = fmaf(v, wv.z, acc[kq * 4 + 2]);
                        acc[kq * 4 + 3] = fmaf(v, wv.w, acc[kq * 4 + 3]);
                    }
                }
        }
        __syncthreads();
    }

    const int gy = y0 + ly, gx = x0 + lx;
    if (gy < H && gx < W) {
        float* lg = out + (size_t)40 * PB[l];
#pragma unroll
        for (int k = 0; k < 20; k++)
            lg[((size_t)(b * 20 + k)) * HW + gy * W + gx] = acc[k];
        out[(size_t)48 * STOT + 2 * PB[l] + (size_t)b * HW + gy * W + gx] = acc[20];
    }
}

// ---------------------------------------------------------------------------
// box_pred(4) with exp(v*scale): reads pre-normalized buffer.
// ---------------------------------------------------------------------------
__global__ __launch_bounds__(256)
void pred_box_k(const float* __restrict__ bin,
                const float* __restrict__ boxw, const float* __restrict__ boxb,
                const float* __restrict__ scales, float* __restrict__ out)
{
    __shared__ __align__(16) float s_in[CICH][18][19];
    __shared__ __align__(16) float s_wk[CICH][9][4];

    const int tid = threadIdx.x;
    const int bx = blockIdx.x;
    int l = 0;
    if (bx >= 49) l = 1;
    if (bx >= 65) l = 2;
    if (bx >= 69) l = 3;
    if (bx >= 70) l = 4;
    const int HSs[5]   = {100, 50, 25, 13, 7};
    const int TBASE[5] = {0, 49, 65, 69, 70};
    const int TXN[5]   = {7, 4, 2, 1, 1};
    const int PB[5]    = {0, 10000, 12500, 13125, 13294};
    const int H = HSs[l], W = H, HW = H * W;
    const int t = bx - TBASE[l];
    const int tX = TXN[l];
    const int ty = t / tX, tx = t - ty * tX;
    const int y0 = ty * 16, x0 = tx * 16;
    const int b = blockIdx.z;
    const int ly = tid >> 4, lx = tid & 15;

    const float* inb = bin + (size_t)1024 * PB[l] + (size_t)((1 * 2 + b) * CHN) * HW;

    float acc[4];
#pragma unroll
    for (int k = 0; k < 4; k++) acc[k] = boxb[k];

    for (int ci0 = 0; ci0 < CHN; ci0 += CICH) {
#pragma unroll 1
        for (int j = tid; j < CICH * 18 * 18; j += 256) {
            int ci = j / 324;
            int r2 = j - ci * 324;
            int iy = r2 / 18, ix = r2 - iy * 18;
            int gy = y0 - 1 + iy, gx = x0 - 1 + ix;
            float v = 0.f;
            if ((unsigned)gy < (unsigned)H && (unsigned)gx < (unsigned)W)
                v = inb[(size_t)(ci0 + ci) * HW + gy * W + gx];
            s_in[ci][iy][ix] = v;
        }
#pragma unroll 1
        for (int j = tid; j < CICH * 36; j += 256) {
            int ci = j / 36;
            int r2 = j - ci * 36;
            int kk = r2 >> 2;
            int k  = r2 & 3;
            s_wk[ci][kk][k] = boxw[((size_t)k * CHN + ci0 + ci) * 9 + kk];
        }
        __syncthreads();
#pragma unroll 2
        for (int ci = 0; ci < CICH; ci++) {
#pragma unroll
            for (int ky = 0; ky < 3; ky++)
#pragma unroll
                for (int kx = 0; kx < 3; kx++) {
                    const float v = s_in[ci][ly + ky][lx + kx];
                    const float4 wv = *(const float4*)&s_wk[ci][ky * 3 + kx][0];
                    acc[0] = fmaf(v, wv.x, acc[0]);
                    acc[1] = fmaf(v, wv.y, acc[1]);
                    acc[2] = fmaf(v, wv.z, acc[2]);
                    acc[3] = fmaf(v, wv.w, acc[3]);
                }
        }
        __syncthreads();
    }

    const int gy = y0 + ly, gx = x0 + lx;
    if (gy < H && gx < W) {
        const float scl = scales[l];
        float* bo = out + (size_t)40 * STOT + 8 * PB[l];
#pragma unroll
        for (int k = 0; k < 4; k++)
            bo[((size_t)(b * 4 + k)) * HW + gy * W + gx] = expf(acc[k] * scl);
    }
}

// ---------------------------------------------------------------------------
extern "C" void kernel_launch(void* const* d_in, const int* in_sizes, int n_in,
                              void* d_out, int out_size)
{
    (void)in_sizes; (void)n_in; (void)out_size;

    Feat5 fp;
    for (int i = 0; i < 5; i++) fp.p[i] = (const float*)d_in[i];
    const float* cls_w  = (const float*)d_in[5];
    const float* cls_g  = (const float*)d_in[6];
    const float* cls_b  = (const float*)d_in[7];
    const float* box_w  = (const float*)d_in[8];
    const float* box_g  = (const float*)d_in[9];
    const float* box_b  = (const float*)d_in[10];
    const float* clsp_w = (const float*)d_in[11];
    const float* clsp_b = (const float*)d_in[12];
    const float* boxp_w = (const float*)d_in[13];
    const float* boxp_b = (const float*)d_in[14];
    const float* ctrp_w = (const float*)d_in[15];
    const float* ctrp_b = (const float*)d_in[16];
    const float* scales = (const float*)d_in[17];
    float* out = (float*)d_out;

    float *bufA, *bufB, *stats, *nsc, *nsh;
    float2* wre;
    cudaGetSymbolAddress((void**)&bufA,  g_bufA);
    cudaGetSymbolAddress((void**)&bufB,  g_bufB);
    cudaGetSymbolAddress((void**)&wre,   g_wre);
    cudaGetSymbolAddress((void**)&stats, g_stats);
    cudaGetSymbolAddress((void**)&nsc,   g_nsc);
    cudaGetSymbolAddress((void**)&nsh,   g_nsh);

    cudaFuncSetAttribute(conv_k<true>,
                         cudaFuncAttributeMaxDynamicSharedMemorySize, SMEM_DYN);
    cudaFuncSetAttribute(conv_k<false>,
                         cudaFuncAttributeMaxDynamicSharedMemorySize, SMEM_DYN);

    const dim3 gconv(97, 4, 4);
    const dim3 gpred(71, 1, 2);
    const int  gapply = (13663232 + 255) / 256;

    zero_k<<<1, 256>>>(stats);
    wre_k<<<9216, 256>>>(cls_w, box_w, wre);

    conv_k<true ><<<gconv, 256, SMEM_DYN>>>(fp, bufB, bufA, wre, 0, stats);
    fin_k<<<20, 256>>>(cls_g,       cls_b,       box_g,       box_b,       stats, nsc, nsh);
    apply_k<<<gapply, 256>>>(bufA, bufB, nsc, nsh);

    conv_k<false><<<gconv, 256, SMEM_DYN>>>(fp, bufB, bufA, wre, 1, stats);
    fin_k<<<20, 256>>>(cls_g + 256, cls_b + 256, box_g + 256, box_b + 256, stats, nsc, nsh);
    apply_k<<<gapply, 256>>>(bufA, bufB, nsc, nsh);

    conv_k<false><<<gconv, 256, SMEM_DYN>>>(fp, bufB, bufA, wre, 2, stats);
    fin_k<<<20, 256>>>(cls_g + 512, cls_b + 512, box_g + 512, box_b + 512, stats, nsc, nsh);
    apply_k<<<gapply, 256>>>(bufA, bufB, nsc, nsh);

    conv_k<false><<<gconv, 256, SMEM_DYN>>>(fp, bufB, bufA, wre, 3, stats);
    fin_k<<<20, 256>>>(cls_g + 768, cls_b + 768, box_g + 768, box_b + 768, stats, nsc, nsh);
    apply_k<<<gapply, 256>>>(bufA, bufB, nsc, nsh);

    pred_cls_k<<<gpred, 256>>>(bufB, clsp_w, clsp_b, ctrp_w, ctrp_b, out);
    pred_box_k<<<gpred, 256>>>(bufB, boxp_w, boxp_b, scales, out);
}